// round 1
// baseline (speedup 1.0000x reference)
#include <cuda_runtime.h>

#define NPTS 131072
#define DD 32
#define KK 64
#define B2E 14.426950408889634f  /* BETA * log2(e), BETA=10 */

// ---------------- device scratch (no allocations allowed) ----------------
__device__ float g_xs[NPTS * DD];          // cluster-sorted copy of x (16 MB)
__device__ unsigned char g_pred[NPTS];
__device__ int   g_counts[KK];
__device__ int   g_offsets[KK + 1];
__device__ int   g_cursor[KK];
__device__ float g_fil[KK];
__device__ float g_sums[KK * DD];
__device__ float g_m2[KK * DD * DD];
__device__ float g_acc[2];

// ---------------- K0: zero accumulators ----------------
__global__ void k_zero() {
    int t = blockIdx.x * blockDim.x + threadIdx.x;
    if (t < KK * DD * DD) g_m2[t] = 0.f;
    if (t < KK * DD) g_sums[t] = 0.f;
    if (t < KK) { g_counts[t] = 0; g_fil[t] = 0.f; }
    if (t < 2) g_acc[t] = 0.f;
}

// ---------------- K1: logits, softmax-filling, argmin, histogram ----------------
__global__ __launch_bounds__(256, 1)
void k_assign(const float* __restrict__ x, const float* __restrict__ centers) {
    __shared__ float sc[KK * DD];
    __shared__ float sccn[KK];
    __shared__ float sfil[KK];
    __shared__ int   shist[KK];
    int t = threadIdx.x;

    {   // load centers (2048 floats) vectorized
        const float4* cv = (const float4*)centers;
        float4* scv = (float4*)sc;
#pragma unroll
        for (int v = 0; v < 2; v++) scv[t * 2 + v] = cv[t * 2 + v];
    }
    if (t < KK) { sfil[t] = 0.f; shist[t] = 0; }
    __syncthreads();
    if (t < KK) {
        float a = 0.f;
#pragma unroll
        for (int d = 0; d < DD; d++) { float c = sc[t * DD + d]; a = fmaf(c, c, a); }
        sccn[t] = a;
    }
    __syncthreads();

    float fil[KK];
#pragma unroll
    for (int k = 0; k < KK; k++) fil[k] = 0.f;

    int gt = blockIdx.x * blockDim.x + t;
    int stride = gridDim.x * blockDim.x;

    for (int n = gt; n < NPTS; n += stride) {
        float xr[DD];
        const float4* xv = (const float4*)(x + (size_t)n * DD);
#pragma unroll
        for (int q = 0; q < DD / 4; q++) {
            float4 v = xv[q];
            xr[4 * q] = v.x; xr[4 * q + 1] = v.y; xr[4 * q + 2] = v.z; xr[4 * q + 3] = v.w;
        }
        // s[k] = ||c_k||^2 - 2 x.c_k   (row-constant ||x||^2 dropped: softmax/argmin invariant)
        float s[KK];
#pragma unroll
        for (int k0 = 0; k0 < KK; k0 += 4) {
            float a0 = 0.f, a1 = 0.f, a2 = 0.f, a3 = 0.f;
#pragma unroll
            for (int q = 0; q < 8; q++) {
                float4 v0 = *(const float4*)(sc + (k0 + 0) * DD + 4 * q);
                float4 v1 = *(const float4*)(sc + (k0 + 1) * DD + 4 * q);
                float4 v2 = *(const float4*)(sc + (k0 + 2) * DD + 4 * q);
                float4 v3 = *(const float4*)(sc + (k0 + 3) * DD + 4 * q);
                float x0 = xr[4 * q], x1 = xr[4 * q + 1], x2 = xr[4 * q + 2], x3 = xr[4 * q + 3];
                a0 = fmaf(x0, v0.x, a0); a0 = fmaf(x1, v0.y, a0); a0 = fmaf(x2, v0.z, a0); a0 = fmaf(x3, v0.w, a0);
                a1 = fmaf(x0, v1.x, a1); a1 = fmaf(x1, v1.y, a1); a1 = fmaf(x2, v1.z, a1); a1 = fmaf(x3, v1.w, a1);
                a2 = fmaf(x0, v2.x, a2); a2 = fmaf(x1, v2.y, a2); a2 = fmaf(x2, v2.z, a2); a2 = fmaf(x3, v2.w, a2);
                a3 = fmaf(x0, v3.x, a3); a3 = fmaf(x1, v3.y, a3); a3 = fmaf(x2, v3.z, a3); a3 = fmaf(x3, v3.w, a3);
            }
            s[k0 + 0] = fmaf(-2.f, a0, sccn[k0 + 0]);
            s[k0 + 1] = fmaf(-2.f, a1, sccn[k0 + 1]);
            s[k0 + 2] = fmaf(-2.f, a2, sccn[k0 + 2]);
            s[k0 + 3] = fmaf(-2.f, a3, sccn[k0 + 3]);
        }
        // min (4 interleaved chains)
        float m0 = s[0], m1 = s[1], m2v = s[2], m3 = s[3];
#pragma unroll
        for (int k = 4; k < KK; k += 4) {
            m0 = fminf(m0, s[k]); m1 = fminf(m1, s[k + 1]);
            m2v = fminf(m2v, s[k + 2]); m3 = fminf(m3, s[k + 3]);
        }
        float mn = fminf(fminf(m0, m1), fminf(m2v, m3));
        // first index equal to mn (downward loop => smallest index wins)
        int am = KK - 1;
#pragma unroll
        for (int k = KK - 2; k >= 0; k--) if (s[k] == mn) am = k;
        // exp + sum (4 partial sums)
        float e0 = 0.f, e1 = 0.f, e2 = 0.f, e3 = 0.f;
#pragma unroll
        for (int k = 0; k < KK; k += 4) {
            float t0, t1, t2, t3;
            asm("ex2.approx.f32 %0, %1;" : "=f"(t0) : "f"((mn - s[k + 0]) * B2E));
            asm("ex2.approx.f32 %0, %1;" : "=f"(t1) : "f"((mn - s[k + 1]) * B2E));
            asm("ex2.approx.f32 %0, %1;" : "=f"(t2) : "f"((mn - s[k + 2]) * B2E));
            asm("ex2.approx.f32 %0, %1;" : "=f"(t3) : "f"((mn - s[k + 3]) * B2E));
            s[k + 0] = t0; s[k + 1] = t1; s[k + 2] = t2; s[k + 3] = t3;
            e0 += t0; e1 += t1; e2 += t2; e3 += t3;
        }
        float inv = 1.0f / ((e0 + e1) + (e2 + e3));
#pragma unroll
        for (int k = 0; k < KK; k++) fil[k] = fmaf(s[k], inv, fil[k]);

        g_pred[n] = (unsigned char)am;
        atomicAdd(&shist[am], 1);
    }

    // block reduce fil: warp butterfly, one lane per k adds to shared
#pragma unroll
    for (int k = 0; k < KK; k++) {
        float v = fil[k];
        v += __shfl_xor_sync(0xffffffffu, v, 16);
        v += __shfl_xor_sync(0xffffffffu, v, 8);
        v += __shfl_xor_sync(0xffffffffu, v, 4);
        v += __shfl_xor_sync(0xffffffffu, v, 2);
        v += __shfl_xor_sync(0xffffffffu, v, 1);
        if ((t & 31) == (k & 31)) atomicAdd(&sfil[k], v);
    }
    __syncthreads();
    if (t < KK) {
        atomicAdd(&g_fil[t], sfil[t]);
        atomicAdd(&g_counts[t], shist[t]);
    }
}

// ---------------- K2: prefix sum (tiny) ----------------
__global__ void k_prefix() {
    if (threadIdx.x == 0) {
        int a = 0;
        for (int k = 0; k < KK; k++) {
            g_offsets[k] = a; g_cursor[k] = a; a += g_counts[k];
        }
        g_offsets[KK] = a;
    }
}

// ---------------- K3: scatter x into cluster-sorted order ----------------
__global__ __launch_bounds__(256)
void k_scatter(const float* __restrict__ x) {
    int n = blockIdx.x * blockDim.x + threadIdx.x;
    if (n >= NPTS) return;
    int k = g_pred[n];
    int pos = atomicAdd(&g_cursor[k], 1);
    const float4* src = (const float4*)(x + (size_t)n * DD);
    float4* dst = (float4*)(g_xs + (size_t)pos * DD);
#pragma unroll
    for (int q = 0; q < DD / 4; q++) dst[q] = src[q];
}

// ---------------- K4: per-cluster sums + second moments (tile GEMM) ----------------
#define TP 64
#define SPLITS 4
__global__ __launch_bounds__(256)
void k_cov() {
    int b = blockIdx.x;
    int k = b >> 2, sp = b & (SPLITS - 1);
    int beg = g_offsets[k], end = g_offsets[k + 1];
    int len = end - beg;
    int chunk = (len + SPLITS - 1) / SPLITS;
    int s0 = beg + sp * chunk;
    int s1 = s0 + chunk; if (s1 > end) s1 = end;
    if (s0 >= s1) return;

    __shared__ float sx[TP * DD];
    int t = threadIdx.x;
    int i = t >> 3;
    int j0 = (t & 7) * 4;
    float m0 = 0.f, m1 = 0.f, m2v = 0.f, m3 = 0.f;
    float ssum = 0.f;

    for (int p0 = s0; p0 < s1; p0 += TP) {
        __syncthreads();
        {   // cooperative vectorized tile load, zero-pad tail
            float4* sv = (float4*)sx;
            const float4* gv = (const float4*)g_xs;
            int lim = s1 * (DD / 4);
#pragma unroll
            for (int v = 0; v < 2; v++) {
                int li = t * 2 + v;
                int gi = p0 * (DD / 4) + li;
                float4 val = make_float4(0.f, 0.f, 0.f, 0.f);
                if (gi < lim) val = gv[gi];
                sv[li] = val;
            }
        }
        __syncthreads();
#pragma unroll
        for (int p = 0; p < TP; p++) {
            float a = sx[p * DD + i];
            float4 bv = *(const float4*)(sx + p * DD + j0);
            m0 = fmaf(a, bv.x, m0); m1 = fmaf(a, bv.y, m1);
            m2v = fmaf(a, bv.z, m2v); m3 = fmaf(a, bv.w, m3);
            if (t < DD) ssum += sx[p * DD + t];   // warp 0 only, uniform
        }
    }
    int base = k * DD * DD + i * DD + j0;
    atomicAdd(&g_m2[base + 0], m0);
    atomicAdd(&g_m2[base + 1], m1);
    atomicAdd(&g_m2[base + 2], m2v);
    atomicAdd(&g_m2[base + 3], m3);
    if (t < DD) atomicAdd(&g_sums[k * DD + t], ssum);
}

// ---------------- K5a: per-cluster stat loss partials ----------------
__global__ __launch_bounds__(256)
void k_stat(const float* __restrict__ means_t, const float* __restrict__ covs_t) {
    int k = blockIdx.x;
    int t = threadIdx.x;
    __shared__ float smean[DD];
    __shared__ float red[8];
    int cnt = g_counts[k];
    float inv = 1.0f / (float)(cnt > 0 ? cnt : 1);
    if (t < DD) smean[t] = g_sums[k * DD + t] * inv;
    __syncthreads();
    float lm = 0.f;
    if (t < DD) { float dm = smean[t] - means_t[k * DD + t]; lm = dm * dm; }
    float lc = 0.f;
#pragma unroll
    for (int r = 0; r < 4; r++) {
        int idx = t + r * 256;
        int ii = idx >> 5, jj = idx & 31;
        float cov = g_m2[k * DD * DD + idx] * inv - smean[ii] * smean[jj];
        float dc = cov - covs_t[k * DD * DD + idx];
        lc = fmaf(dc, dc, lc);
    }
    float v = lm * (1.0f / (KK * DD)) + lc * (1.0f / (KK * DD * DD));
    v += __shfl_xor_sync(0xffffffffu, v, 16);
    v += __shfl_xor_sync(0xffffffffu, v, 8);
    v += __shfl_xor_sync(0xffffffffu, v, 4);
    v += __shfl_xor_sync(0xffffffffu, v, 2);
    v += __shfl_xor_sync(0xffffffffu, v, 1);
    if ((t & 31) == 0) red[t >> 5] = v;
    __syncthreads();
    if (t == 0) {
        float s = 0.f;
#pragma unroll
        for (int w = 0; w < 8; w++) s += red[w];
        atomicAdd(&g_acc[0], s);
    }
}

// ---------------- K5b: filling loss + final scalar ----------------
__global__ void k_final(const float* __restrict__ fil_t, float* __restrict__ out) {
    __shared__ float red[2];
    int t = threadIdx.x;  // 64 threads
    float f = g_fil[t] * (1.0f / NPTS) - fil_t[t];
    float v = f * f;
    v += __shfl_xor_sync(0xffffffffu, v, 16);
    v += __shfl_xor_sync(0xffffffffu, v, 8);
    v += __shfl_xor_sync(0xffffffffu, v, 4);
    v += __shfl_xor_sync(0xffffffffu, v, 2);
    v += __shfl_xor_sync(0xffffffffu, v, 1);
    if ((t & 31) == 0) red[t >> 5] = v;
    __syncthreads();
    if (t == 0) out[0] = (red[0] + red[1]) * (1.0f / KK) + g_acc[0];
}

// ---------------- launcher ----------------
extern "C" void kernel_launch(void* const* d_in, const int* in_sizes, int n_in,
                              void* d_out, int out_size) {
    const float* x       = (const float*)d_in[0];
    const float* centers = (const float*)d_in[1];
    const float* fil_t   = (const float*)d_in[2];
    const float* means_t = (const float*)d_in[3];
    const float* covs_t  = (const float*)d_in[4];
    float* out = (float*)d_out;
    (void)in_sizes; (void)n_in; (void)out_size;

    k_zero<<<256, 256>>>();
    k_assign<<<148, 256>>>(x, centers);
    k_prefix<<<1, 32>>>();
    k_scatter<<<NPTS / 256, 256>>>(x);
    k_cov<<<KK * SPLITS, 256>>>();
    k_stat<<<KK, 256>>>(means_t, covs_t);
    k_final<<<1, 64>>>(fil_t, out);
}

// round 3
// speedup vs baseline: 1.0557x; 1.0557x over previous
#include <cuda_runtime.h>

#define NPTS 131072
#define DD 32
#define KK 64
#define B2E 14.426950408889634f  /* BETA * log2(e), BETA=10 */
#define NBLK 148                 /* k_assign grid */
#define NPAIRS (NBLK * 128)      /* 18944 pairs, 128 per block */
#define NREP 32                  /* scatter cursor replicas */

// ---------------- device scratch ----------------
__device__ float g_xs[NPTS * DD];          // cluster-sorted copy of x (16 MB)
__device__ unsigned char g_pred[NPTS];
__device__ int   g_counts[KK];
__device__ int   g_counts2[KK * NREP];
__device__ int   g_cursor2[KK * NREP];
__device__ int   g_offsets[KK + 1];
__device__ float g_fil[KK];
__device__ float g_sums[KK * DD];
__device__ float g_m2[KK * DD * DD];
__device__ float g_acc[2];

// ---------------- K0: zero accumulators ----------------
__global__ void k_zero() {
    int t = blockIdx.x * blockDim.x + threadIdx.x;
    if (t < KK * DD * DD) g_m2[t] = 0.f;
    if (t < KK * DD) g_sums[t] = 0.f;
    if (t < KK * NREP) g_counts2[t] = 0;
    if (t < KK) g_fil[t] = 0.f;
    if (t < 2) g_acc[t] = 0.f;
}

// ---------------- K1: logits, softmax-filling, argmin, histogram ----------------
// Pair-split: lanes (2i, 2i+1) share point i; each lane handles 32 clusters.
__global__ __launch_bounds__(256, 1)
void k_assign(const float* __restrict__ x, const float* __restrict__ centers) {
    __shared__ float sc[KK * DD];
    __shared__ float sccn[KK];
    __shared__ float sfil[KK];
    __shared__ int   shist[KK];
    int t = threadIdx.x;

    {   // load centers (2048 floats) vectorized
        const float4* cv = (const float4*)centers;
        float4* scv = (float4*)sc;
#pragma unroll
        for (int v = 0; v < 2; v++) scv[t * 2 + v] = cv[t * 2 + v];
    }
    if (t < KK) { sfil[t] = 0.f; shist[t] = 0; }
    __syncthreads();
    if (t < KK) {
        float a = 0.f;
#pragma unroll
        for (int d = 0; d < DD; d++) { float c = sc[t * DD + d]; a = fmaf(c, c, a); }
        sccn[t] = a;
    }
    __syncthreads();

    int half = t & 1;                       // which 32-cluster half
    int kofs = half * 32;
    const float* cb = sc + kofs * DD;

    float fil[32];
#pragma unroll
    for (int k = 0; k < 32; k++) fil[k] = 0.f;

    int pair0 = (blockIdx.x * 256 + t) >> 1;

    for (int n = pair0; n < NPTS; n += NPAIRS) {
        float xr[DD];
        const float4* xv = (const float4*)(x + (size_t)n * DD);
#pragma unroll
        for (int q = 0; q < DD / 4; q++) {
            float4 v = xv[q];
            xr[4 * q] = v.x; xr[4 * q + 1] = v.y; xr[4 * q + 2] = v.z; xr[4 * q + 3] = v.w;
        }
        // s[k] = ||c_k||^2 - 2 x.c_k  for my 32 clusters
        float s[32];
#pragma unroll
        for (int g = 0; g < 8; g++) {
            int k0 = g * 4;
            float a0 = 0.f, a1 = 0.f, a2 = 0.f, a3 = 0.f;
#pragma unroll
            for (int q = 0; q < 8; q++) {
                float4 v0 = *(const float4*)(cb + (k0 + 0) * DD + 4 * q);
                float4 v1 = *(const float4*)(cb + (k0 + 1) * DD + 4 * q);
                float4 v2 = *(const float4*)(cb + (k0 + 2) * DD + 4 * q);
                float4 v3 = *(const float4*)(cb + (k0 + 3) * DD + 4 * q);
                float x0 = xr[4 * q], x1 = xr[4 * q + 1], x2 = xr[4 * q + 2], x3 = xr[4 * q + 3];
                a0 = fmaf(x0, v0.x, a0); a0 = fmaf(x1, v0.y, a0); a0 = fmaf(x2, v0.z, a0); a0 = fmaf(x3, v0.w, a0);
                a1 = fmaf(x0, v1.x, a1); a1 = fmaf(x1, v1.y, a1); a1 = fmaf(x2, v1.z, a1); a1 = fmaf(x3, v1.w, a1);
                a2 = fmaf(x0, v2.x, a2); a2 = fmaf(x1, v2.y, a2); a2 = fmaf(x2, v2.z, a2); a2 = fmaf(x3, v2.w, a2);
                a3 = fmaf(x0, v3.x, a3); a3 = fmaf(x1, v3.y, a3); a3 = fmaf(x2, v3.z, a3); a3 = fmaf(x3, v3.w, a3);
            }
            s[k0 + 0] = fmaf(-2.f, a0, sccn[kofs + k0 + 0]);
            s[k0 + 1] = fmaf(-2.f, a1, sccn[kofs + k0 + 1]);
            s[k0 + 2] = fmaf(-2.f, a2, sccn[kofs + k0 + 2]);
            s[k0 + 3] = fmaf(-2.f, a3, sccn[kofs + k0 + 3]);
        }
        // local min over my 32
        float m0 = s[0], m1 = s[1], m2v = s[2], m3 = s[3];
#pragma unroll
        for (int k = 4; k < 32; k += 4) {
            m0 = fminf(m0, s[k]); m1 = fminf(m1, s[k + 1]);
            m2v = fminf(m2v, s[k + 2]); m3 = fminf(m3, s[k + 3]);
        }
        float mloc = fminf(fminf(m0, m1), fminf(m2v, m3));
        int amloc = 31;
#pragma unroll
        for (int k = 30; k >= 0; k--) if (s[k] == mloc) amloc = k;
        int amg = kofs + amloc;
        // combine across pair
        float mo = __shfl_xor_sync(0xffffffffu, mloc, 1);
        int   ao = __shfl_xor_sync(0xffffffffu, amg, 1);
        float mn = fminf(mloc, mo);
        int am;
        if (mloc < mo) am = amg;
        else if (mo < mloc) am = ao;
        else am = amg < ao ? amg : ao;
        // exp relative to global min + pair-sum
        float e0 = 0.f, e1 = 0.f, e2 = 0.f, e3 = 0.f;
#pragma unroll
        for (int k = 0; k < 32; k += 4) {
            float t0, t1, t2, t3;
            asm("ex2.approx.f32 %0, %1;" : "=f"(t0) : "f"((mn - s[k + 0]) * B2E));
            asm("ex2.approx.f32 %0, %1;" : "=f"(t1) : "f"((mn - s[k + 1]) * B2E));
            asm("ex2.approx.f32 %0, %1;" : "=f"(t2) : "f"((mn - s[k + 2]) * B2E));
            asm("ex2.approx.f32 %0, %1;" : "=f"(t3) : "f"((mn - s[k + 3]) * B2E));
            s[k + 0] = t0; s[k + 1] = t1; s[k + 2] = t2; s[k + 3] = t3;
            e0 += t0; e1 += t1; e2 += t2; e3 += t3;
        }
        float es = (e0 + e1) + (e2 + e3);
        es += __shfl_xor_sync(0xffffffffu, es, 1);
        float inv = 1.0f / es;
#pragma unroll
        for (int k = 0; k < 32; k++) fil[k] = fmaf(s[k], inv, fil[k]);

        if (half == 0) {
            g_pred[n] = (unsigned char)am;
            atomicAdd(&shist[am], 1);
        }
    }

    // reduce fil across lanes of same parity (even lanes hold k, odd hold k+32)
#pragma unroll
    for (int k = 0; k < 32; k++) {
        float v = fil[k];
        v += __shfl_xor_sync(0xffffffffu, v, 2);
        v += __shfl_xor_sync(0xffffffffu, v, 4);
        v += __shfl_xor_sync(0xffffffffu, v, 8);
        v += __shfl_xor_sync(0xffffffffu, v, 16);
        int lane = t & 31;
        if (lane == 0) atomicAdd(&sfil[k], v);
        else if (lane == 1) atomicAdd(&sfil[k + 32], v);
    }
    __syncthreads();
    if (t < KK) {
        atomicAdd(&g_fil[t], sfil[t]);
        atomicAdd(&g_counts2[t * NREP + (blockIdx.x & (NREP - 1))], shist[t]);
    }
}

// ---------------- K2: prefix over 64 clusters x 32 replicas ----------------
__global__ void k_prefix() {
    __shared__ int csum[KK];
    int t = threadIdx.x;   // 64 threads
    int c[NREP];
    int total = 0;
#pragma unroll
    for (int r = 0; r < NREP; r++) { c[r] = g_counts2[t * NREP + r]; total += c[r]; }
    csum[t] = total;
    __syncthreads();
    if (t == 0) {
        int a = 0;
        for (int k = 0; k < KK; k++) { g_offsets[k] = a; a += csum[k]; }
        g_offsets[KK] = a;
    }
    __syncthreads();
    int a = g_offsets[t];
#pragma unroll
    for (int r = 0; r < NREP; r++) { g_cursor2[t * NREP + r] = a; a += c[r]; }
    g_counts[t] = total;
}

// ---------------- K3: scatter x into cluster-sorted order ----------------
__global__ __launch_bounds__(256)
void k_scatter(const float* __restrict__ x) {
    int n = blockIdx.x * blockDim.x + threadIdx.x;
    if (n >= NPTS) return;
    int k = g_pred[n];
    // point n was counted by K1 block (pair >> 7); pair = n mod NPAIRS (128 pairs/block)
    int rep = ((n % NPAIRS) >> 7) & (NREP - 1);
    int pos = atomicAdd(&g_cursor2[k * NREP + rep], 1);
    const float4* src = (const float4*)(x + (size_t)n * DD);
    float4* dst = (float4*)(g_xs + (size_t)pos * DD);
#pragma unroll
    for (int q = 0; q < DD / 4; q++) dst[q] = src[q];
}

// ---------------- K4: per-cluster sums + second moments (tile GEMM) ----------------
#define TP 64
#define SPLITS 8
__global__ __launch_bounds__(256)
void k_cov() {
    int b = blockIdx.x;
    int k = b >> 3, sp = b & (SPLITS - 1);
    int beg = g_offsets[k], end = g_offsets[k + 1];
    int len = end - beg;
    int chunk = (len + SPLITS - 1) / SPLITS;
    int s0 = beg + sp * chunk;
    int s1 = s0 + chunk; if (s1 > end) s1 = end;
    if (s0 >= s1) return;

    __shared__ float sx[TP * DD];
    int t = threadIdx.x;
    int i = t >> 3;
    int j0 = (t & 7) * 4;
    float m0 = 0.f, m1 = 0.f, m2v = 0.f, m3 = 0.f;
    float ssum = 0.f;

    for (int p0 = s0; p0 < s1; p0 += TP) {
        __syncthreads();
        {   // cooperative vectorized tile load, zero-pad tail
            float4* sv = (float4*)sx;
            const float4* gv = (const float4*)g_xs;
            int lim = s1 * (DD / 4);
#pragma unroll
            for (int v = 0; v < 2; v++) {
                int li = t * 2 + v;
                int gi = p0 * (DD / 4) + li;
                float4 val = make_float4(0.f, 0.f, 0.f, 0.f);
                if (gi < lim) val = gv[gi];
                sv[li] = val;
            }
        }
        __syncthreads();
#pragma unroll
        for (int p = 0; p < TP; p++) {
            float a = sx[p * DD + i];
            float4 bv = *(const float4*)(sx + p * DD + j0);
            m0 = fmaf(a, bv.x, m0); m1 = fmaf(a, bv.y, m1);
            m2v = fmaf(a, bv.z, m2v); m3 = fmaf(a, bv.w, m3);
            if (t < DD) ssum += sx[p * DD + t];   // warp 0 only
        }
    }
    int base = k * DD * DD + i * DD + j0;
    atomicAdd(&g_m2[base + 0], m0);
    atomicAdd(&g_m2[base + 1], m1);
    atomicAdd(&g_m2[base + 2], m2v);
    atomicAdd(&g_m2[base + 3], m3);
    if (t < DD) atomicAdd(&g_sums[k * DD + t], ssum);
}

// ---------------- K5a: per-cluster stat loss partials ----------------
__global__ __launch_bounds__(256)
void k_stat(const float* __restrict__ means_t, const float* __restrict__ covs_t) {
    int k = blockIdx.x;
    int t = threadIdx.x;
    __shared__ float smean[DD];
    __shared__ float red[8];
    int cnt = g_counts[k];
    float inv = 1.0f / (float)(cnt > 0 ? cnt : 1);
    if (t < DD) smean[t] = g_sums[k * DD + t] * inv;
    __syncthreads();
    float lm = 0.f;
    if (t < DD) { float dm = smean[t] - means_t[k * DD + t]; lm = dm * dm; }
    float lc = 0.f;
#pragma unroll
    for (int r = 0; r < 4; r++) {
        int idx = t + r * 256;
        int ii = idx >> 5, jj = idx & 31;
        float cov = g_m2[k * DD * DD + idx] * inv - smean[ii] * smean[jj];
        float dc = cov - covs_t[k * DD * DD + idx];
        lc = fmaf(dc, dc, lc);
    }
    float v = lm * (1.0f / (KK * DD)) + lc * (1.0f / (KK * DD * DD));
    v += __shfl_xor_sync(0xffffffffu, v, 16);
    v += __shfl_xor_sync(0xffffffffu, v, 8);
    v += __shfl_xor_sync(0xffffffffu, v, 4);
    v += __shfl_xor_sync(0xffffffffu, v, 2);
    v += __shfl_xor_sync(0xffffffffu, v, 1);
    if ((t & 31) == 0) red[t >> 5] = v;
    __syncthreads();
    if (t == 0) {
        float s = 0.f;
#pragma unroll
        for (int w = 0; w < 8; w++) s += red[w];
        atomicAdd(&g_acc[0], s);
    }
}

// ---------------- K5b: filling loss + final scalar ----------------
__global__ void k_final(const float* __restrict__ fil_t, float* __restrict__ out) {
    __shared__ float red[2];
    int t = threadIdx.x;  // 64 threads
    float f = g_fil[t] * (1.0f / NPTS) - fil_t[t];
    float v = f * f;
    v += __shfl_xor_sync(0xffffffffu, v, 16);
    v += __shfl_xor_sync(0xffffffffu, v, 8);
    v += __shfl_xor_sync(0xffffffffu, v, 4);
    v += __shfl_xor_sync(0xffffffffu, v, 2);
    v += __shfl_xor_sync(0xffffffffu, v, 1);
    if ((t & 31) == 0) red[t >> 5] = v;
    __syncthreads();
    if (t == 0) out[0] = (red[0] + red[1]) * (1.0f / KK) + g_acc[0];
}

// ---------------- launcher ----------------
extern "C" void kernel_launch(void* const* d_in, const int* in_sizes, int n_in,
                              void* d_out, int out_size) {
    const float* x       = (const float*)d_in[0];
    const float* centers = (const float*)d_in[1];
    const float* fil_t   = (const float*)d_in[2];
    const float* means_t = (const float*)d_in[3];
    const float* covs_t  = (const float*)d_in[4];
    float* out = (float*)d_out;
    (void)in_sizes; (void)n_in; (void)out_size;

    k_zero<<<256, 256>>>();
    k_assign<<<NBLK, 256>>>(x, centers);
    k_prefix<<<1, 64>>>();
    k_scatter<<<NPTS / 256, 256>>>(x);
    k_cov<<<KK * SPLITS, 256>>>();
    k_stat<<<KK, 256>>>(means_t, covs_t);
    k_final<<<1, 64>>>(fil_t, out);
}

// round 4
// speedup vs baseline: 4.5385x; 4.2992x over previous
#include <cuda_runtime.h>

#define NPTS 131072
#define DD 32
#define KK 64
#define B2E 14.426950408889634f  /* BETA * log2(e), BETA=10 */
#define NBLK2 296                /* k_assign grid: 2 blocks/SM */
#define NWARPS (NBLK2 * 8)       /* 2368 counting warps */
#define NREP 32                  /* scatter cursor replicas */

// ---------------- device scratch ----------------
__device__ float g_xs[NPTS * DD];          // cluster-sorted copy of x (16 MB)
__device__ unsigned char g_pred[NPTS];
__device__ int   g_counts[KK];
__device__ int   g_counts2[KK * NREP];
__device__ int   g_cursor2[KK * NREP];
__device__ int   g_offsets[KK + 1];
__device__ float g_fil[KK];
__device__ float g_sums[KK * DD];
__device__ float g_m2[KK * DD * DD];
__device__ float g_acc[2];

// ---------------- K0: zero accumulators ----------------
__global__ void k_zero() {
    int t = blockIdx.x * blockDim.x + threadIdx.x;
    if (t < KK * DD * DD) g_m2[t] = 0.f;
    if (t < KK * DD) g_sums[t] = 0.f;
    if (t < KK * NREP) g_counts2[t] = 0;
    if (t < KK) g_fil[t] = 0.f;
    if (t < 2) g_acc[t] = 0.f;
}

// no-op: shifts k_assign into the ncu-profiled launch slot
__global__ void k_nop() {}

// ---------------- K1: logits, softmax-filling, argmin, histogram ----------------
// Lane l holds center rows l and l+32 in REGISTERS. Warp processes 4 points per
// iteration: points staged in shared, read back as uniform broadcast LDS.128.
__global__ __launch_bounds__(256, 2)
void k_assign(const float* __restrict__ x, const float* __restrict__ centers) {
    __shared__ float sfil[KK];
    __shared__ int   shist[KK];
    __shared__ float sxw[8][4][DD];   // per-warp staging: 4 points x 32 dims

    int t = threadIdx.x, w = t >> 5, l = t & 31;

    // centers rows l and l+32 -> registers (one-time, L1/L2 absorbs)
    float c0[DD], c1[DD];
    {
        const float4* r0 = (const float4*)(centers + l * DD);
        const float4* r1 = (const float4*)(centers + (l + 32) * DD);
#pragma unroll
        for (int q = 0; q < 8; q++) {
            float4 a = r0[q];
            c0[4 * q] = a.x; c0[4 * q + 1] = a.y; c0[4 * q + 2] = a.z; c0[4 * q + 3] = a.w;
            float4 b = r1[q];
            c1[4 * q] = b.x; c1[4 * q + 1] = b.y; c1[4 * q + 2] = b.z; c1[4 * q + 3] = b.w;
        }
    }
    float cn0 = 0.f, cn1 = 0.f;
#pragma unroll
    for (int d = 0; d < DD; d++) {
        cn0 = fmaf(c0[d], c0[d], cn0);
        cn1 = fmaf(c1[d], c1[d], cn1);
    }

    if (t < KK) { sfil[t] = 0.f; shist[t] = 0; }
    __syncthreads();

    float fil0 = 0.f, fil1 = 0.f;
    int W = blockIdx.x * 8 + w;

    for (int n0 = W * 4; n0 < NPTS; n0 += NWARPS * 4) {
        float xp[4];
#pragma unroll
        for (int p = 0; p < 4; p++) xp[p] = x[(size_t)(n0 + p) * DD + l];
        __syncwarp();
#pragma unroll
        for (int p = 0; p < 4; p++) sxw[w][p][l] = xp[p];
        __syncwarp();

        unsigned pred4 = 0;
#pragma unroll
        for (int p = 0; p < 4; p++) {
            float d0 = 0.f, d1 = 0.f;
#pragma unroll
            for (int q = 0; q < 8; q++) {
                float4 xv = *(const float4*)&sxw[w][p][4 * q];   // uniform broadcast
                d0 = fmaf(c0[4 * q + 0], xv.x, d0);
                d0 = fmaf(c0[4 * q + 1], xv.y, d0);
                d0 = fmaf(c0[4 * q + 2], xv.z, d0);
                d0 = fmaf(c0[4 * q + 3], xv.w, d0);
                d1 = fmaf(c1[4 * q + 0], xv.x, d1);
                d1 = fmaf(c1[4 * q + 1], xv.y, d1);
                d1 = fmaf(c1[4 * q + 2], xv.z, d1);
                d1 = fmaf(c1[4 * q + 3], xv.w, d1);
            }
            float s0 = fmaf(-2.f, d0, cn0);   // ||c||^2 - 2 x.c  (||x||^2 invariant)
            float s1 = fmaf(-2.f, d1, cn1);

            // warp-wide min over 64 values (2 per lane)
            float v = fminf(s0, s1);
#pragma unroll
            for (int off = 16; off; off >>= 1)
                v = fminf(v, __shfl_xor_sync(0xffffffffu, v, off));
            // smallest index attaining the exact min
            int idx = (s0 == v) ? l : ((s1 == v) ? l + 32 : 1024);
#pragma unroll
            for (int off = 16; off; off >>= 1)
                idx = min(idx, __shfl_xor_sync(0xffffffffu, idx, off));

            // softmax contributions
            float e0, e1;
            asm("ex2.approx.f32 %0, %1;" : "=f"(e0) : "f"((v - s0) * B2E));
            asm("ex2.approx.f32 %0, %1;" : "=f"(e1) : "f"((v - s1) * B2E));
            float es = e0 + e1;
#pragma unroll
            for (int off = 16; off; off >>= 1)
                es += __shfl_xor_sync(0xffffffffu, es, off);
            float inv;
            asm("rcp.approx.f32 %0, %1;" : "=f"(inv) : "f"(es));
            fil0 = fmaf(e0, inv, fil0);
            fil1 = fmaf(e1, inv, fil1);

            pred4 |= (unsigned)idx << (8 * p);
            if (l == p) atomicAdd(&shist[idx], 1);   // spread hist atomics over lanes 0..3
        }
        if (l == 0) *(unsigned*)(g_pred + n0) = pred4;   // n0 is 4-aligned
    }

    // fil: lane l owns clusters l and l+32 -> direct spread shared atomics
    atomicAdd(&sfil[l], fil0);
    atomicAdd(&sfil[l + 32], fil1);
    __syncthreads();
    if (t < KK) {
        atomicAdd(&g_fil[t], sfil[t]);
        atomicAdd(&g_counts2[t * NREP + (blockIdx.x & (NREP - 1))], shist[t]);
    }
}

// ---------------- K2: prefix over 64 clusters x 32 replicas ----------------
__global__ void k_prefix() {
    __shared__ int csum[KK];
    int t = threadIdx.x;   // 64 threads
    int c[NREP];
    int total = 0;
#pragma unroll
    for (int r = 0; r < NREP; r++) { c[r] = g_counts2[t * NREP + r]; total += c[r]; }
    csum[t] = total;
    __syncthreads();
    if (t == 0) {
        int a = 0;
        for (int k = 0; k < KK; k++) { g_offsets[k] = a; a += csum[k]; }
        g_offsets[KK] = a;
    }
    __syncthreads();
    int a = g_offsets[t];
#pragma unroll
    for (int r = 0; r < NREP; r++) { g_cursor2[t * NREP + r] = a; a += c[r]; }
    g_counts[t] = total;
}

// ---------------- K3: scatter x into cluster-sorted order (4 pts/thread) ----------------
__global__ __launch_bounds__(256)
void k_scatter(const float* __restrict__ x) {
    int i0 = (blockIdx.x * 256 + threadIdx.x) * 4;
    if (i0 >= NPTS) return;
    unsigned pr = *(const unsigned*)(g_pred + i0);
    // points [i0, i0+3] were counted by warp W = (i0>>2) % NWARPS, replica (W>>3)&31
    int rep = (((i0 >> 2) % NWARPS) >> 3) & (NREP - 1);
    int pos[4];
#pragma unroll
    for (int p = 0; p < 4; p++) {
        int k = (pr >> (8 * p)) & 255;
        pos[p] = atomicAdd(&g_cursor2[k * NREP + rep], 1);
    }
#pragma unroll
    for (int p = 0; p < 4; p++) {
        const float4* src = (const float4*)(x + (size_t)(i0 + p) * DD);
        float4* dst = (float4*)(g_xs + (size_t)pos[p] * DD);
#pragma unroll
        for (int q = 0; q < 8; q++) dst[q] = src[q];
    }
}

// ---------------- K4: per-cluster sums + second moments (tile GEMM) ----------------
#define TP 64
#define SPLITS 8
__global__ __launch_bounds__(256)
void k_cov() {
    int b = blockIdx.x;
    int k = b >> 3, sp = b & (SPLITS - 1);
    int beg = g_offsets[k], end = g_offsets[k + 1];
    int len = end - beg;
    int chunk = (len + SPLITS - 1) / SPLITS;
    int s0 = beg + sp * chunk;
    int s1 = s0 + chunk; if (s1 > end) s1 = end;
    if (s0 >= s1) return;

    __shared__ float sx[TP * DD];
    int t = threadIdx.x;
    int i = t >> 3;
    int j0 = (t & 7) * 4;
    float m0 = 0.f, m1 = 0.f, m2v = 0.f, m3 = 0.f;
    float ssum = 0.f;

    for (int p0 = s0; p0 < s1; p0 += TP) {
        __syncthreads();
        {   // cooperative vectorized tile load, zero-pad tail
            float4* sv = (float4*)sx;
            const float4* gv = (const float4*)g_xs;
            int lim = s1 * (DD / 4);
#pragma unroll
            for (int v = 0; v < 2; v++) {
                int li = t * 2 + v;
                int gi = p0 * (DD / 4) + li;
                float4 val = make_float4(0.f, 0.f, 0.f, 0.f);
                if (gi < lim) val = gv[gi];
                sv[li] = val;
            }
        }
        __syncthreads();
#pragma unroll
        for (int p = 0; p < TP; p++) {
            float a = sx[p * DD + i];
            float4 bv = *(const float4*)(sx + p * DD + j0);
            m0 = fmaf(a, bv.x, m0); m1 = fmaf(a, bv.y, m1);
            m2v = fmaf(a, bv.z, m2v); m3 = fmaf(a, bv.w, m3);
            if (t < DD) ssum += sx[p * DD + t];   // warp 0 only
        }
    }
    int base = k * DD * DD + i * DD + j0;
    atomicAdd(&g_m2[base + 0], m0);
    atomicAdd(&g_m2[base + 1], m1);
    atomicAdd(&g_m2[base + 2], m2v);
    atomicAdd(&g_m2[base + 3], m3);
    if (t < DD) atomicAdd(&g_sums[k * DD + t], ssum);
}

// ---------------- K5a: per-cluster stat loss partials ----------------
__global__ __launch_bounds__(256)
void k_stat(const float* __restrict__ means_t, const float* __restrict__ covs_t) {
    int k = blockIdx.x;
    int t = threadIdx.x;
    __shared__ float smean[DD];
    __shared__ float red[8];
    int cnt = g_counts[k];
    float inv = 1.0f / (float)(cnt > 0 ? cnt : 1);
    if (t < DD) smean[t] = g_sums[k * DD + t] * inv;
    __syncthreads();
    float lm = 0.f;
    if (t < DD) { float dm = smean[t] - means_t[k * DD + t]; lm = dm * dm; }
    float lc = 0.f;
#pragma unroll
    for (int r = 0; r < 4; r++) {
        int idx = t + r * 256;
        int ii = idx >> 5, jj = idx & 31;
        float cov = g_m2[k * DD * DD + idx] * inv - smean[ii] * smean[jj];
        float dc = cov - covs_t[k * DD * DD + idx];
        lc = fmaf(dc, dc, lc);
    }
    float v = lm * (1.0f / (KK * DD)) + lc * (1.0f / (KK * DD * DD));
    v += __shfl_xor_sync(0xffffffffu, v, 16);
    v += __shfl_xor_sync(0xffffffffu, v, 8);
    v += __shfl_xor_sync(0xffffffffu, v, 4);
    v += __shfl_xor_sync(0xffffffffu, v, 2);
    v += __shfl_xor_sync(0xffffffffu, v, 1);
    if ((t & 31) == 0) red[t >> 5] = v;
    __syncthreads();
    if (t == 0) {
        float s = 0.f;
#pragma unroll
        for (int w = 0; w < 8; w++) s += red[w];
        atomicAdd(&g_acc[0], s);
    }
}

// ---------------- K5b: filling loss + final scalar ----------------
__global__ void k_final(const float* __restrict__ fil_t, float* __restrict__ out) {
    __shared__ float red[2];
    int t = threadIdx.x;  // 64 threads
    float f = g_fil[t] * (1.0f / NPTS) - fil_t[t];
    float v = f * f;
    v += __shfl_xor_sync(0xffffffffu, v, 16);
    v += __shfl_xor_sync(0xffffffffu, v, 8);
    v += __shfl_xor_sync(0xffffffffu, v, 4);
    v += __shfl_xor_sync(0xffffffffu, v, 2);
    v += __shfl_xor_sync(0xffffffffu, v, 1);
    if ((t & 31) == 0) red[t >> 5] = v;
    __syncthreads();
    if (t == 0) out[0] = (red[0] + red[1]) * (1.0f / KK) + g_acc[0];
}

// ---------------- launcher ----------------
extern "C" void kernel_launch(void* const* d_in, const int* in_sizes, int n_in,
                              void* d_out, int out_size) {
    const float* x       = (const float*)d_in[0];
    const float* centers = (const float*)d_in[1];
    const float* fil_t   = (const float*)d_in[2];
    const float* means_t = (const float*)d_in[3];
    const float* covs_t  = (const float*)d_in[4];
    float* out = (float*)d_out;
    (void)in_sizes; (void)n_in; (void)out_size;

    k_zero<<<256, 256>>>();
    k_nop<<<1, 32>>>();     // shift profiled slot
    k_nop<<<1, 32>>>();     // -> 4th launch is k_assign
    k_assign<<<NBLK2, 256>>>(x, centers);
    k_prefix<<<1, 64>>>();
    k_scatter<<<NPTS / 1024, 256>>>(x);
    k_cov<<<KK * SPLITS, 256>>>();
    k_stat<<<KK, 256>>>(means_t, covs_t);
    k_final<<<1, 64>>>(fil_t, out);
}

// round 7
// speedup vs baseline: 4.6999x; 1.0356x over previous
#include <cuda_runtime.h>

#define NPTS 131072
#define DD 32
#define KK 64
#define B2E 14.426950408889634f  /* BETA * log2(e), BETA=10 */
#define NBLK2 296                /* k_assign grid: 2 blocks/SM */
#define NWARPS (NBLK2 * 8)       /* 2368 counting warps */
#define NREP 32                  /* scatter cursor replicas */

// ---------------- device scratch (zero-initialized at load; every kernel
// leaves its accumulators re-zeroed => graph replays start clean) ----------
__device__ float g_xs[NPTS * DD];
__device__ unsigned char g_pred[NPTS];
__device__ int   g_counts[KK];
__device__ int   g_counts2[KK * NREP];
__device__ int   g_cursor2[KK * NREP];
__device__ int   g_offsets[KK + 1];
__device__ float g_fil[KK];
__device__ float g_sums[KK * DD];
__device__ float g_m2[KK * DD * DD];
__device__ float g_acc[2];

// order-preserving float<->u32 key (min of key == min of float, bijective)
__device__ __forceinline__ unsigned ordkey(float f) {
    unsigned u = __float_as_uint(f);
    return u ^ (unsigned)(((int)u >> 31) | 0x80000000);
}
__device__ __forceinline__ float unord(unsigned k) {
    unsigned u = (k & 0x80000000u) ? (k ^ 0x80000000u) : ~k;
    return __uint_as_float(u);
}

// ---------------- K1: logits, softmax-filling, argmin, histogram ----------------
// Lane l holds center rows l and l+32 in registers. Warp processes 4 points
// per iteration; all reductions for the 4 points run interleaved (ILP=4),
// min/argmin via single REDUX.SYNC ops.
__global__ __launch_bounds__(256, 2)
void k_assign(const float* __restrict__ x, const float* __restrict__ centers) {
    __shared__ float sfil[KK];
    __shared__ int   shist[KK];
    __shared__ float sxw[8][4][DD];

    int t = threadIdx.x, w = t >> 5, l = t & 31;

    float c0[DD], c1[DD];
    {
        const float4* r0 = (const float4*)(centers + l * DD);
        const float4* r1 = (const float4*)(centers + (l + 32) * DD);
#pragma unroll
        for (int q = 0; q < 8; q++) {
            float4 a = r0[q];
            c0[4 * q] = a.x; c0[4 * q + 1] = a.y; c0[4 * q + 2] = a.z; c0[4 * q + 3] = a.w;
            float4 b = r1[q];
            c1[4 * q] = b.x; c1[4 * q + 1] = b.y; c1[4 * q + 2] = b.z; c1[4 * q + 3] = b.w;
        }
    }
    float cn0 = 0.f, cn1 = 0.f;
#pragma unroll
    for (int d = 0; d < DD; d++) {
        cn0 = fmaf(c0[d], c0[d], cn0);
        cn1 = fmaf(c1[d], c1[d], cn1);
    }

    if (t < KK) { sfil[t] = 0.f; shist[t] = 0; }
    __syncthreads();

    float fil0 = 0.f, fil1 = 0.f;
    int W = blockIdx.x * 8 + w;

    for (int n0 = W * 4; n0 < NPTS; n0 += NWARPS * 4) {
        float xp[4];
#pragma unroll
        for (int p = 0; p < 4; p++) xp[p] = x[(size_t)(n0 + p) * DD + l];
        __syncwarp();
#pragma unroll
        for (int p = 0; p < 4; p++) sxw[w][p][l] = xp[p];
        __syncwarp();

        float s0a[4], s1a[4];
#pragma unroll
        for (int p = 0; p < 4; p++) {
            float d0 = 0.f, d1 = 0.f;
#pragma unroll
            for (int q = 0; q < 8; q++) {
                float4 xv = *(const float4*)&sxw[w][p][4 * q];
                d0 = fmaf(c0[4 * q + 0], xv.x, d0);
                d0 = fmaf(c0[4 * q + 1], xv.y, d0);
                d0 = fmaf(c0[4 * q + 2], xv.z, d0);
                d0 = fmaf(c0[4 * q + 3], xv.w, d0);
                d1 = fmaf(c1[4 * q + 0], xv.x, d1);
                d1 = fmaf(c1[4 * q + 1], xv.y, d1);
                d1 = fmaf(c1[4 * q + 2], xv.z, d1);
                d1 = fmaf(c1[4 * q + 3], xv.w, d1);
            }
            s0a[p] = fmaf(-2.f, d0, cn0);   // ||c||^2 - 2 x.c  (||x||^2 invariant)
            s1a[p] = fmaf(-2.f, d1, cn1);
        }

        // min over 64 per point: single REDUX on orderable keys (ILP=4)
        unsigned k0v[4], k1v[4], mk[4];
#pragma unroll
        for (int p = 0; p < 4; p++) { k0v[p] = ordkey(s0a[p]); k1v[p] = ordkey(s1a[p]); }
#pragma unroll
        for (int p = 0; p < 4; p++)
            mk[p] = __reduce_min_sync(0xffffffffu, min(k0v[p], k1v[p]));
        // smallest index attaining the min (exact key equality)
        int id[4];
#pragma unroll
        for (int p = 0; p < 4; p++) {
            unsigned cand = (k0v[p] == mk[p]) ? (unsigned)l
                          : ((k1v[p] == mk[p]) ? (unsigned)(l + 32) : 1024u);
            id[p] = (int)__reduce_min_sync(0xffffffffu, cand);
        }

        float e0[4], e1[4], es[4];
#pragma unroll
        for (int p = 0; p < 4; p++) {
            float mn = unord(mk[p]);
            asm("ex2.approx.f32 %0, %1;" : "=f"(e0[p]) : "f"((mn - s0a[p]) * B2E));
            asm("ex2.approx.f32 %0, %1;" : "=f"(e1[p]) : "f"((mn - s1a[p]) * B2E));
            es[p] = e0[p] + e1[p];
        }
#pragma unroll
        for (int off = 16; off; off >>= 1) {
#pragma unroll
            for (int p = 0; p < 4; p++)
                es[p] += __shfl_xor_sync(0xffffffffu, es[p], off);
        }

        unsigned pred4 = 0;
#pragma unroll
        for (int p = 0; p < 4; p++) {
            float inv;
            asm("rcp.approx.f32 %0, %1;" : "=f"(inv) : "f"(es[p]));
            fil0 = fmaf(e0[p], inv, fil0);
            fil1 = fmaf(e1[p], inv, fil1);
            pred4 |= (unsigned)id[p] << (8 * p);
            if (l == p) atomicAdd(&shist[id[p]], 1);
        }
        if (l == 0) *(unsigned*)(g_pred + n0) = pred4;
    }

    atomicAdd(&sfil[l], fil0);
    atomicAdd(&sfil[l + 32], fil1);
    __syncthreads();
    if (t < KK) {
        atomicAdd(&g_fil[t], sfil[t]);
        atomicAdd(&g_counts2[t * NREP + (blockIdx.x & (NREP - 1))], shist[t]);
    }
}

// ---------------- K2: prefix over 64 clusters x 32 replicas (+re-zero) ----------------
__global__ void k_prefix() {
    __shared__ int csum[KK];
    int t = threadIdx.x;   // 64 threads
    int c[NREP];
    int total = 0;
#pragma unroll
    for (int r = 0; r < NREP; r++) {
        c[r] = g_counts2[t * NREP + r];
        g_counts2[t * NREP + r] = 0;      // consumer-zeroing for next run
        total += c[r];
    }
    csum[t] = total;
    __syncthreads();
    if (t == 0) {
        int a = 0;
        for (int k = 0; k < KK; k++) { g_offsets[k] = a; a += csum[k]; }
        g_offsets[KK] = a;
    }
    __syncthreads();
    int a = g_offsets[t];
#pragma unroll
    for (int r = 0; r < NREP; r++) { g_cursor2[t * NREP + r] = a; a += c[r]; }
    g_counts[t] = total;
}

// ---------------- K3: scatter x into cluster-sorted order (4 pts/thread) ----------------
__global__ __launch_bounds__(256)
void k_scatter(const float* __restrict__ x) {
    int i0 = (blockIdx.x * 256 + threadIdx.x) * 4;
    if (i0 >= NPTS) return;
    unsigned pr = *(const unsigned*)(g_pred + i0);
    int rep = (((i0 >> 2) % NWARPS) >> 3) & (NREP - 1);
    int pos[4];
#pragma unroll
    for (int p = 0; p < 4; p++) {
        int k = (pr >> (8 * p)) & 255;
        pos[p] = atomicAdd(&g_cursor2[k * NREP + rep], 1);
    }
#pragma unroll
    for (int p = 0; p < 4; p++) {
        const float4* src = (const float4*)(x + (size_t)(i0 + p) * DD);
        float4* dst = (float4*)(g_xs + (size_t)pos[p] * DD);
#pragma unroll
        for (int q = 0; q < 8; q++) dst[q] = src[q];
    }
}

// ---------------- K4: per-cluster sums + second moments (2x4 register block) ----------------
#define TP 64
#define SPLITS 8
__global__ __launch_bounds__(128)
void k_cov() {
    int b = blockIdx.x;
    int k = b >> 3, sp = b & (SPLITS - 1);
    int beg = g_offsets[k], end = g_offsets[k + 1];
    int len = end - beg;
    int chunk = (len + SPLITS - 1) / SPLITS;
    int s0 = beg + sp * chunk;
    int s1 = s0 + chunk; if (s1 > end) s1 = end;
    if (s0 >= s1) return;

    __shared__ float sx[TP * DD];
    int t = threadIdx.x;               // 128 threads
    int i = t >> 3;                    // rows i and i+16
    int j0 = (t & 7) * 4;              // 4 cols
    float a00 = 0.f, a01 = 0.f, a02 = 0.f, a03 = 0.f;
    float a10 = 0.f, a11 = 0.f, a12 = 0.f, a13 = 0.f;
    float ssum = 0.f;

    for (int p0 = s0; p0 < s1; p0 += TP) {
        __syncthreads();
        {   // lane-contiguous coalesced tile load (512 float4 / 128 thr = 4 each)
            float4* sv = (float4*)sx;
            const float4* gv = (const float4*)g_xs;
            int lim = s1 * (DD / 4);
#pragma unroll
            for (int v = 0; v < 4; v++) {
                int li = v * 128 + t;
                int gi = p0 * (DD / 4) + li;
                float4 val = make_float4(0.f, 0.f, 0.f, 0.f);
                if (gi < lim) val = gv[gi];
                sv[li] = val;
            }
        }
        __syncthreads();
        if (t < DD) {                  // warp 0: column sums for this tile
#pragma unroll
            for (int p = 0; p < TP; p++) ssum += sx[p * DD + t];
        }
#pragma unroll
        for (int p = 0; p < TP; p++) {
            float r0 = sx[p * DD + i];
            float r1 = sx[p * DD + i + 16];
            float4 bv = *(const float4*)(sx + p * DD + j0);
            a00 = fmaf(r0, bv.x, a00); a01 = fmaf(r0, bv.y, a01);
            a02 = fmaf(r0, bv.z, a02); a03 = fmaf(r0, bv.w, a03);
            a10 = fmaf(r1, bv.x, a10); a11 = fmaf(r1, bv.y, a11);
            a12 = fmaf(r1, bv.z, a12); a13 = fmaf(r1, bv.w, a13);
        }
    }
    int base0 = k * DD * DD + i * DD + j0;
    int base1 = base0 + 16 * DD;
    atomicAdd(&g_m2[base0 + 0], a00); atomicAdd(&g_m2[base0 + 1], a01);
    atomicAdd(&g_m2[base0 + 2], a02); atomicAdd(&g_m2[base0 + 3], a03);
    atomicAdd(&g_m2[base1 + 0], a10); atomicAdd(&g_m2[base1 + 1], a11);
    atomicAdd(&g_m2[base1 + 2], a12); atomicAdd(&g_m2[base1 + 3], a13);
    if (t < DD) atomicAdd(&g_sums[k * DD + t], ssum);
}

// ---------------- K5a: per-cluster stat loss partials (+re-zero m2/sums) ----------------
__global__ __launch_bounds__(256)
void k_stat(const float* __restrict__ means_t, const float* __restrict__ covs_t) {
    int k = blockIdx.x;
    int t = threadIdx.x;
    __shared__ float smean[DD];
    __shared__ float red[8];
    int cnt = g_counts[k];
    float inv = 1.0f / (float)(cnt > 0 ? cnt : 1);
    if (t < DD) smean[t] = g_sums[k * DD + t] * inv;
    __syncthreads();
    float lm = 0.f;
    if (t < DD) {
        float dm = smean[t] - means_t[k * DD + t];
        lm = dm * dm;
        g_sums[k * DD + t] = 0.f;         // consumer-zeroing
    }
    float lc = 0.f;
#pragma unroll
    for (int r = 0; r < 4; r++) {
        int idx = t + r * 256;
        int ii = idx >> 5, jj = idx & 31;
        float cov = g_m2[k * DD * DD + idx] * inv - smean[ii] * smean[jj];
        g_m2[k * DD * DD + idx] = 0.f;    // consumer-zeroing
        float dc = cov - covs_t[k * DD * DD + idx];
        lc = fmaf(dc, dc, lc);
    }
    float v = lm * (1.0f / (KK * DD)) + lc * (1.0f / (KK * DD * DD));
    v += __shfl_xor_sync(0xffffffffu, v, 16);
    v += __shfl_xor_sync(0xffffffffu, v, 8);
    v += __shfl_xor_sync(0xffffffffu, v, 4);
    v += __shfl_xor_sync(0xffffffffu, v, 2);
    v += __shfl_xor_sync(0xffffffffu, v, 1);
    if ((t & 31) == 0) red[t >> 5] = v;
    __syncthreads();
    if (t == 0) {
        float s = 0.f;
#pragma unroll
        for (int w = 0; w < 8; w++) s += red[w];
        atomicAdd(&g_acc[0], s);
    }
}

// ---------------- K5b: filling loss + final scalar (+re-zero fil/acc) ----------------
__global__ void k_final(const float* __restrict__ fil_t, float* __restrict__ out) {
    __shared__ float red[2];
    int t = threadIdx.x;  // 64 threads
    float f = g_fil[t] * (1.0f / NPTS) - fil_t[t];
    g_fil[t] = 0.f;                       // consumer-zeroing
    float v = f * f;
    v += __shfl_xor_sync(0xffffffffu, v, 16);
    v += __shfl_xor_sync(0xffffffffu, v, 8);
    v += __shfl_xor_sync(0xffffffffu, v, 4);
    v += __shfl_xor_sync(0xffffffffu, v, 2);
    v += __shfl_xor_sync(0xffffffffu, v, 1);
    if ((t & 31) == 0) red[t >> 5] = v;
    __syncthreads();
    if (t == 0) {
        float a = g_acc[0];
        g_acc[0] = 0.f;                   // consumer-zeroing
        out[0] = (red[0] + red[1]) * (1.0f / KK) + a;
    }
}

// ---------------- launcher (k_cov lands in profiled launch slot #4) ----------------
extern "C" void kernel_launch(void* const* d_in, const int* in_sizes, int n_in,
                              void* d_out, int out_size) {
    const float* x       = (const float*)d_in[0];
    const float* centers = (const float*)d_in[1];
    const float* fil_t   = (const float*)d_in[2];
    const float* means_t = (const float*)d_in[3];
    const float* covs_t  = (const float*)d_in[4];
    float* out = (float*)d_out;
    (void)in_sizes; (void)n_in; (void)out_size;

    k_assign<<<NBLK2, 256>>>(x, centers);
    k_prefix<<<1, 64>>>();
    k_scatter<<<NPTS / 1024, 256>>>(x);
    k_cov<<<KK * SPLITS, 128>>>();
    k_stat<<<KK, 256>>>(means_t, covs_t);
    k_final<<<1, 64>>>(fil_t, out);
}

// round 8
// speedup vs baseline: 6.2371x; 1.3271x over previous
#include <cuda_runtime.h>

#define NPTS 131072
#define DD 32
#define KK 64
#define B2E 14.426950408889634f  /* BETA * log2(e), BETA=10 */
#define NBLK2 296                /* k_assign grid: 2 blocks/SM */
#define NWARPS (NBLK2 * 8)       /* 2368 counting warps */
#define NREP 32                  /* scatter cursor replicas */
#define TILE 64                  /* k_cov tile rows */

// ---------------- device scratch (zero-initialized at load; every kernel
// leaves its accumulators re-zeroed => graph replays start clean) ----------
__device__ float g_xs[NPTS * DD];
__device__ unsigned char g_pred[NPTS];
__device__ int   g_counts[KK];
__device__ int   g_counts2[KK * NREP];
__device__ int   g_cursor2[KK * NREP];
__device__ int   g_offsets[KK + 1];
__device__ float g_fil[KK];
__device__ float g_sums[KK * DD];
__device__ float g_m2[KK * DD * DD];
__device__ float g_acc[2];

// order-preserving float<->u32 key (min of key == min of float, bijective)
__device__ __forceinline__ unsigned ordkey(float f) {
    unsigned u = __float_as_uint(f);
    return u ^ (unsigned)(((int)u >> 31) | 0x80000000);
}
__device__ __forceinline__ float unord(unsigned k) {
    unsigned u = (k & 0x80000000u) ? (k ^ 0x80000000u) : ~k;
    return __uint_as_float(u);
}

// ---------------- K1: logits, softmax-filling, argmin, histogram ----------------
__global__ __launch_bounds__(256, 2)
void k_assign(const float* __restrict__ x, const float* __restrict__ centers) {
    __shared__ float sfil[KK];
    __shared__ int   shist[KK];
    __shared__ float sxw[8][4][DD];

    int t = threadIdx.x, w = t >> 5, l = t & 31;

    float c0[DD], c1[DD];
    {
        const float4* r0 = (const float4*)(centers + l * DD);
        const float4* r1 = (const float4*)(centers + (l + 32) * DD);
#pragma unroll
        for (int q = 0; q < 8; q++) {
            float4 a = r0[q];
            c0[4 * q] = a.x; c0[4 * q + 1] = a.y; c0[4 * q + 2] = a.z; c0[4 * q + 3] = a.w;
            float4 b = r1[q];
            c1[4 * q] = b.x; c1[4 * q + 1] = b.y; c1[4 * q + 2] = b.z; c1[4 * q + 3] = b.w;
        }
    }
    float cn0 = 0.f, cn1 = 0.f;
#pragma unroll
    for (int d = 0; d < DD; d++) {
        cn0 = fmaf(c0[d], c0[d], cn0);
        cn1 = fmaf(c1[d], c1[d], cn1);
    }

    if (t < KK) { sfil[t] = 0.f; shist[t] = 0; }
    __syncthreads();

    float fil0 = 0.f, fil1 = 0.f;
    int W = blockIdx.x * 8 + w;

    for (int n0 = W * 4; n0 < NPTS; n0 += NWARPS * 4) {
        float xp[4];
#pragma unroll
        for (int p = 0; p < 4; p++) xp[p] = x[(size_t)(n0 + p) * DD + l];
        __syncwarp();
#pragma unroll
        for (int p = 0; p < 4; p++) sxw[w][p][l] = xp[p];
        __syncwarp();

        float s0a[4], s1a[4];
#pragma unroll
        for (int p = 0; p < 4; p++) {
            float d0 = 0.f, d1 = 0.f;
#pragma unroll
            for (int q = 0; q < 8; q++) {
                float4 xv = *(const float4*)&sxw[w][p][4 * q];
                d0 = fmaf(c0[4 * q + 0], xv.x, d0);
                d0 = fmaf(c0[4 * q + 1], xv.y, d0);
                d0 = fmaf(c0[4 * q + 2], xv.z, d0);
                d0 = fmaf(c0[4 * q + 3], xv.w, d0);
                d1 = fmaf(c1[4 * q + 0], xv.x, d1);
                d1 = fmaf(c1[4 * q + 1], xv.y, d1);
                d1 = fmaf(c1[4 * q + 2], xv.z, d1);
                d1 = fmaf(c1[4 * q + 3], xv.w, d1);
            }
            s0a[p] = fmaf(-2.f, d0, cn0);
            s1a[p] = fmaf(-2.f, d1, cn1);
        }

        unsigned k0v[4], k1v[4], mk[4];
#pragma unroll
        for (int p = 0; p < 4; p++) { k0v[p] = ordkey(s0a[p]); k1v[p] = ordkey(s1a[p]); }
#pragma unroll
        for (int p = 0; p < 4; p++)
            mk[p] = __reduce_min_sync(0xffffffffu, min(k0v[p], k1v[p]));
        int id[4];
#pragma unroll
        for (int p = 0; p < 4; p++) {
            unsigned cand = (k0v[p] == mk[p]) ? (unsigned)l
                          : ((k1v[p] == mk[p]) ? (unsigned)(l + 32) : 1024u);
            id[p] = (int)__reduce_min_sync(0xffffffffu, cand);
        }

        float e0[4], e1[4], es[4];
#pragma unroll
        for (int p = 0; p < 4; p++) {
            float mn = unord(mk[p]);
            asm("ex2.approx.f32 %0, %1;" : "=f"(e0[p]) : "f"((mn - s0a[p]) * B2E));
            asm("ex2.approx.f32 %0, %1;" : "=f"(e1[p]) : "f"((mn - s1a[p]) * B2E));
            es[p] = e0[p] + e1[p];
        }
#pragma unroll
        for (int off = 16; off; off >>= 1) {
#pragma unroll
            for (int p = 0; p < 4; p++)
                es[p] += __shfl_xor_sync(0xffffffffu, es[p], off);
        }

        unsigned pred4 = 0;
#pragma unroll
        for (int p = 0; p < 4; p++) {
            float inv;
            asm("rcp.approx.f32 %0, %1;" : "=f"(inv) : "f"(es[p]));
            fil0 = fmaf(e0[p], inv, fil0);
            fil1 = fmaf(e1[p], inv, fil1);
            pred4 |= (unsigned)id[p] << (8 * p);
            if (l == p) atomicAdd(&shist[id[p]], 1);
        }
        if (l == 0) *(unsigned*)(g_pred + n0) = pred4;
    }

    atomicAdd(&sfil[l], fil0);
    atomicAdd(&sfil[l + 32], fil1);
    __syncthreads();
    if (t < KK) {
        atomicAdd(&g_fil[t], sfil[t]);
        atomicAdd(&g_counts2[t * NREP + (blockIdx.x & (NREP - 1))], shist[t]);
    }
}

// ---------------- K2: prefix over 64 clusters x 32 replicas (+re-zero) ----------------
__global__ void k_prefix() {
    __shared__ int csum[KK];
    int t = threadIdx.x;   // 64 threads
    int c[NREP];
    int total = 0;
#pragma unroll
    for (int r = 0; r < NREP; r++) {
        c[r] = g_counts2[t * NREP + r];
        g_counts2[t * NREP + r] = 0;
        total += c[r];
    }
    csum[t] = total;
    __syncthreads();
    if (t == 0) {
        int a = 0;
        for (int k = 0; k < KK; k++) { g_offsets[k] = a; a += csum[k]; }
        g_offsets[KK] = a;
    }
    __syncthreads();
    int a = g_offsets[t];
#pragma unroll
    for (int r = 0; r < NREP; r++) { g_cursor2[t * NREP + r] = a; a += c[r]; }
    g_counts[t] = total;
}

// ---------------- K3: scatter x into cluster-sorted order (4 pts/thread) ----------------
__global__ __launch_bounds__(256)
void k_scatter(const float* __restrict__ x) {
    int i0 = (blockIdx.x * 256 + threadIdx.x) * 4;
    if (i0 >= NPTS) return;
    unsigned pr = *(const unsigned*)(g_pred + i0);
    int rep = (((i0 >> 2) % NWARPS) >> 3) & (NREP - 1);
    int pos[4];
#pragma unroll
    for (int p = 0; p < 4; p++) {
        int k = (pr >> (8 * p)) & 255;
        pos[p] = atomicAdd(&g_cursor2[k * NREP + rep], 1);
    }
#pragma unroll
    for (int p = 0; p < 4; p++) {
        const float4* src = (const float4*)(x + (size_t)(i0 + p) * DD);
        float4* dst = (float4*)(g_xs + (size_t)pos[p] * DD);
#pragma unroll
        for (int q = 0; q < 8; q++) dst[q] = src[q];
    }
}

// ---------------- K4: uniform 64-row tiles over sorted array, segmented ----------------
// 2048 blocks x 128 threads; ~97% of tiles lie inside one cluster (fast path).
__global__ __launch_bounds__(128)
void k_cov() {
    __shared__ float sx[TILE * DD];
    int t = threadIdx.x;
    int p0 = blockIdx.x * TILE;

    {   // coalesced tile load: 512 float4 / 128 threads = 4 each (all rows valid)
        float4* sv = (float4*)sx;
        const float4* gv = (const float4*)g_xs + (size_t)p0 * (DD / 4);
#pragma unroll
        for (int v = 0; v < 4; v++) sv[v * 128 + t] = gv[v * 128 + t];
    }
    __syncthreads();

    // cluster containing row p0: largest c with offsets[c] <= p0
    int lo_c = 0, hi_c = KK;
    while (lo_c + 1 < hi_c) {
        int mid = (lo_c + hi_c) >> 1;
        if (g_offsets[mid] <= p0) lo_c = mid; else hi_c = mid;
    }
    int c = lo_c;

    int i = t >> 3;            // rows i, i+16
    int j0 = (t & 7) * 4;      // 4 cols

    int segStart = p0;
    int tileEnd = p0 + TILE;
    while (segStart < tileEnd) {
        int segEnd = g_offsets[c + 1];
        if (segEnd > tileEnd) segEnd = tileEnd;
        int lo = segStart - p0, hi = segEnd - p0;
        if (hi > lo) {
            float a00 = 0.f, a01 = 0.f, a02 = 0.f, a03 = 0.f;
            float a10 = 0.f, a11 = 0.f, a12 = 0.f, a13 = 0.f;
            float ssum = 0.f;
            if (lo == 0 && hi == TILE) {
                if (t < DD) {
#pragma unroll
                    for (int p = 0; p < TILE; p++) ssum += sx[p * DD + t];
                }
#pragma unroll 16
                for (int p = 0; p < TILE; p++) {
                    float r0 = sx[p * DD + i];
                    float r1 = sx[p * DD + i + 16];
                    float4 bv = *(const float4*)(sx + p * DD + j0);
                    a00 = fmaf(r0, bv.x, a00); a01 = fmaf(r0, bv.y, a01);
                    a02 = fmaf(r0, bv.z, a02); a03 = fmaf(r0, bv.w, a03);
                    a10 = fmaf(r1, bv.x, a10); a11 = fmaf(r1, bv.y, a11);
                    a12 = fmaf(r1, bv.z, a12); a13 = fmaf(r1, bv.w, a13);
                }
            } else {
                if (t < DD) {
                    for (int p = lo; p < hi; p++) ssum += sx[p * DD + t];
                }
                for (int p = lo; p < hi; p++) {
                    float r0 = sx[p * DD + i];
                    float r1 = sx[p * DD + i + 16];
                    float4 bv = *(const float4*)(sx + p * DD + j0);
                    a00 = fmaf(r0, bv.x, a00); a01 = fmaf(r0, bv.y, a01);
                    a02 = fmaf(r0, bv.z, a02); a03 = fmaf(r0, bv.w, a03);
                    a10 = fmaf(r1, bv.x, a10); a11 = fmaf(r1, bv.y, a11);
                    a12 = fmaf(r1, bv.z, a12); a13 = fmaf(r1, bv.w, a13);
                }
            }
            int base0 = c * DD * DD + i * DD + j0;
            int base1 = base0 + 16 * DD;
            atomicAdd(&g_m2[base0 + 0], a00); atomicAdd(&g_m2[base0 + 1], a01);
            atomicAdd(&g_m2[base0 + 2], a02); atomicAdd(&g_m2[base0 + 3], a03);
            atomicAdd(&g_m2[base1 + 0], a10); atomicAdd(&g_m2[base1 + 1], a11);
            atomicAdd(&g_m2[base1 + 2], a12); atomicAdd(&g_m2[base1 + 3], a13);
            if (t < DD) atomicAdd(&g_sums[c * DD + t], ssum);
        }
        segStart = segEnd;
        c++;
    }
}

// ---------------- K5a: per-cluster stat loss partials (+re-zero m2/sums) ----------------
__global__ __launch_bounds__(256)
void k_stat(const float* __restrict__ means_t, const float* __restrict__ covs_t) {
    int k = blockIdx.x;
    int t = threadIdx.x;
    __shared__ float smean[DD];
    __shared__ float red[8];
    int cnt = g_counts[k];
    float inv = 1.0f / (float)(cnt > 0 ? cnt : 1);
    if (t < DD) smean[t] = g_sums[k * DD + t] * inv;
    __syncthreads();
    float lm = 0.f;
    if (t < DD) {
        float dm = smean[t] - means_t[k * DD + t];
        lm = dm * dm;
        g_sums[k * DD + t] = 0.f;
    }
    float lc = 0.f;
#pragma unroll
    for (int r = 0; r < 4; r++) {
        int idx = t + r * 256;
        int ii = idx >> 5, jj = idx & 31;
        float cov = g_m2[k * DD * DD + idx] * inv - smean[ii] * smean[jj];
        g_m2[k * DD * DD + idx] = 0.f;
        float dc = cov - covs_t[k * DD * DD + idx];
        lc = fmaf(dc, dc, lc);
    }
    float v = lm * (1.0f / (KK * DD)) + lc * (1.0f / (KK * DD * DD));
    v += __shfl_xor_sync(0xffffffffu, v, 16);
    v += __shfl_xor_sync(0xffffffffu, v, 8);
    v += __shfl_xor_sync(0xffffffffu, v, 4);
    v += __shfl_xor_sync(0xffffffffu, v, 2);
    v += __shfl_xor_sync(0xffffffffu, v, 1);
    if ((t & 31) == 0) red[t >> 5] = v;
    __syncthreads();
    if (t == 0) {
        float s = 0.f;
#pragma unroll
        for (int w = 0; w < 8; w++) s += red[w];
        atomicAdd(&g_acc[0], s);
    }
}

// ---------------- K5b: filling loss + final scalar (+re-zero fil/acc) ----------------
__global__ void k_final(const float* __restrict__ fil_t, float* __restrict__ out) {
    __shared__ float red[2];
    int t = threadIdx.x;  // 64 threads
    float f = g_fil[t] * (1.0f / NPTS) - fil_t[t];
    g_fil[t] = 0.f;
    float v = f * f;
    v += __shfl_xor_sync(0xffffffffu, v, 16);
    v += __shfl_xor_sync(0xffffffffu, v, 8);
    v += __shfl_xor_sync(0xffffffffu, v, 4);
    v += __shfl_xor_sync(0xffffffffu, v, 2);
    v += __shfl_xor_sync(0xffffffffu, v, 1);
    if ((t & 31) == 0) red[t >> 5] = v;
    __syncthreads();
    if (t == 0) {
        float a = g_acc[0];
        g_acc[0] = 0.f;
        out[0] = (red[0] + red[1]) * (1.0f / KK) + a;
    }
}

// ---------------- launcher (k_cov is profiled launch slot #4) ----------------
extern "C" void kernel_launch(void* const* d_in, const int* in_sizes, int n_in,
                              void* d_out, int out_size) {
    const float* x       = (const float*)d_in[0];
    const float* centers = (const float*)d_in[1];
    const float* fil_t   = (const float*)d_in[2];
    const float* means_t = (const float*)d_in[3];
    const float* covs_t  = (const float*)d_in[4];
    float* out = (float*)d_out;
    (void)in_sizes; (void)n_in; (void)out_size;

    k_assign<<<NBLK2, 256>>>(x, centers);
    k_prefix<<<1, 64>>>();
    k_scatter<<<NPTS / 1024, 256>>>(x);
    k_cov<<<NPTS / TILE, 128>>>();
    k_stat<<<KK, 256>>>(means_t, covs_t);
    k_final<<<1, 64>>>(fil_t, out);
}

// round 10
// speedup vs baseline: 6.5792x; 1.0548x over previous
#include <cuda_runtime.h>

#define NPTS 131072
#define DD 32
#define KK 64
#define B2E 14.426950408889634f  /* BETA * log2(e), BETA=10 */
#define NBLK2 740                /* k_assign grid: 5 blocks/SM */
#define NWARPS (NBLK2 * 8)       /* 5920 counting warps */
#define NREP 32                  /* scatter cursor replicas */
#define TILE 64                  /* k_cov tile rows */

// ---------------- device scratch (zero-initialized at load; every kernel
// leaves its accumulators re-zeroed => graph replays start clean) ----------
__device__ float g_xs[NPTS * DD];
__device__ unsigned char g_pred[NPTS];
__device__ int   g_counts[KK];
__device__ int   g_counts2[KK * NREP];
__device__ int   g_cursor2[KK * NREP];
__device__ int   g_offsets[KK + 1];
__device__ float g_fil[KK];
__device__ float g_sums[KK * DD];
__device__ float g_m2[KK * DD * DD];
__device__ float g_acc[2];

// order-preserving float<->u32 key (min of key == min of float, bijective)
__device__ __forceinline__ unsigned ordkey(float f) {
    unsigned u = __float_as_uint(f);
    return u ^ (unsigned)(((int)u >> 31) | 0x80000000);
}
__device__ __forceinline__ float unord(unsigned k) {
    unsigned u = (k & 0x80000000u) ? (k ^ 0x80000000u) : ~k;
    return __uint_as_float(u);
}

// ---------------- K1: logits, softmax-filling, argmin, histogram ----------------
// Centers live in XOR-swizzled shared (row r, logical chunk q stored at
// r*32 + (q^(r&7))*4) -> lane-distinct LDS.128 reads are conflict-free.
// Lane l handles clusters l and l+32; warp batches 4 points; c-loads hoisted
// over the point batch (2 c-loads + 4 x-loads per q).
__global__ __launch_bounds__(256, 5)
void k_assign(const float* __restrict__ x, const float* __restrict__ centers) {
    __shared__ float sc[KK * DD];     // swizzled centers
    __shared__ float scn[KK];
    __shared__ float sfil[KK];
    __shared__ int   shist[KK];
    __shared__ float sxw[8][4][DD];

    int t = threadIdx.x, w = t >> 5, l = t & 31;

    // load + swizzle centers: 512 float4 chunks, 2 per thread
#pragma unroll
    for (int v = 0; v < 2; v++) {
        int idx = v * 256 + t;            // chunk id: row r = idx>>3, q = idx&7
        int r = idx >> 3, q = idx & 7;
        float4 val = ((const float4*)centers)[idx];
        int qs = q ^ (r & 7);
        *(float4*)&sc[r * DD + qs * 4] = val;
    }
    __syncthreads();
    if (t < KK) {
        float a = 0.f;
#pragma unroll
        for (int q = 0; q < 8; q++) {
            int qs = q ^ (t & 7);
            float4 v = *(const float4*)&sc[t * DD + qs * 4];
            a = fmaf(v.x, v.x, fmaf(v.y, v.y, fmaf(v.z, v.z, fmaf(v.w, v.w, a))));
        }
        scn[t] = a;
        sfil[t] = 0.f; shist[t] = 0;
    }
    __syncthreads();

    float cn0 = scn[l], cn1 = scn[l + 32];
    const float* c0base = sc + l * DD;
    const float* c1base = sc + (l + 32) * DD;
    int sw = (l & 7);

    float fil0 = 0.f, fil1 = 0.f;
    int W = blockIdx.x * 8 + w;

    for (int n0 = W * 4; n0 < NPTS; n0 += NWARPS * 4) {
        float xp[4];
#pragma unroll
        for (int p = 0; p < 4; p++) xp[p] = x[(size_t)(n0 + p) * DD + l];
        __syncwarp();
#pragma unroll
        for (int p = 0; p < 4; p++) sxw[w][p][l] = xp[p];
        __syncwarp();

        float d0[4] = {0.f, 0.f, 0.f, 0.f};
        float d1[4] = {0.f, 0.f, 0.f, 0.f};
#pragma unroll
        for (int q = 0; q < 8; q++) {
            int qs = (q ^ sw) * 4;
            float4 cv0 = *(const float4*)&c0base[qs];
            float4 cv1 = *(const float4*)&c1base[qs];
#pragma unroll
            for (int p = 0; p < 4; p++) {
                float4 xv = *(const float4*)&sxw[w][p][q * 4];   // broadcast
                d0[p] = fmaf(cv0.x, xv.x, d0[p]);
                d0[p] = fmaf(cv0.y, xv.y, d0[p]);
                d0[p] = fmaf(cv0.z, xv.z, d0[p]);
                d0[p] = fmaf(cv0.w, xv.w, d0[p]);
                d1[p] = fmaf(cv1.x, xv.x, d1[p]);
                d1[p] = fmaf(cv1.y, xv.y, d1[p]);
                d1[p] = fmaf(cv1.z, xv.z, d1[p]);
                d1[p] = fmaf(cv1.w, xv.w, d1[p]);
            }
        }

        float s0a[4], s1a[4];
#pragma unroll
        for (int p = 0; p < 4; p++) {
            s0a[p] = fmaf(-2.f, d0[p], cn0);   // ||c||^2 - 2 x.c (||x||^2 invariant)
            s1a[p] = fmaf(-2.f, d1[p], cn1);
        }

        unsigned k0v[4], k1v[4], mk[4];
#pragma unroll
        for (int p = 0; p < 4; p++) { k0v[p] = ordkey(s0a[p]); k1v[p] = ordkey(s1a[p]); }
#pragma unroll
        for (int p = 0; p < 4; p++)
            mk[p] = __reduce_min_sync(0xffffffffu, min(k0v[p], k1v[p]));
        int id[4];
#pragma unroll
        for (int p = 0; p < 4; p++) {
            unsigned cand = (k0v[p] == mk[p]) ? (unsigned)l
                          : ((k1v[p] == mk[p]) ? (unsigned)(l + 32) : 1024u);
            id[p] = (int)__reduce_min_sync(0xffffffffu, cand);
        }

        float e0[4], e1[4], es[4];
#pragma unroll
        for (int p = 0; p < 4; p++) {
            float mn = unord(mk[p]);
            asm("ex2.approx.f32 %0, %1;" : "=f"(e0[p]) : "f"((mn - s0a[p]) * B2E));
            asm("ex2.approx.f32 %0, %1;" : "=f"(e1[p]) : "f"((mn - s1a[p]) * B2E));
            es[p] = e0[p] + e1[p];
        }
#pragma unroll
        for (int off = 16; off; off >>= 1) {
#pragma unroll
            for (int p = 0; p < 4; p++)
                es[p] += __shfl_xor_sync(0xffffffffu, es[p], off);
        }

        unsigned pred4 = 0;
#pragma unroll
        for (int p = 0; p < 4; p++) {
            float inv;
            asm("rcp.approx.f32 %0, %1;" : "=f"(inv) : "f"(es[p]));
            fil0 = fmaf(e0[p], inv, fil0);
            fil1 = fmaf(e1[p], inv, fil1);
            pred4 |= (unsigned)id[p] << (8 * p);
            if (l == p) atomicAdd(&shist[id[p]], 1);
        }
        if (l == 0) *(unsigned*)(g_pred + n0) = pred4;
    }

    atomicAdd(&sfil[l], fil0);
    atomicAdd(&sfil[l + 32], fil1);
    __syncthreads();
    if (t < KK) {
        atomicAdd(&g_fil[t], sfil[t]);
        atomicAdd(&g_counts2[t * NREP + (blockIdx.x & (NREP - 1))], shist[t]);
    }
}

// ---------------- K2: prefix over 64 clusters x 32 replicas (+re-zero) ----------------
__global__ void k_prefix() {
    __shared__ int csum[KK];
    int t = threadIdx.x;   // 64 threads
    int c[NREP];
    int total = 0;
#pragma unroll
    for (int r = 0; r < NREP; r++) {
        c[r] = g_counts2[t * NREP + r];
        g_counts2[t * NREP + r] = 0;
        total += c[r];
    }
    csum[t] = total;
    __syncthreads();
    if (t == 0) {
        int a = 0;
        for (int k = 0; k < KK; k++) { g_offsets[k] = a; a += csum[k]; }
        g_offsets[KK] = a;
    }
    __syncthreads();
    int a = g_offsets[t];
#pragma unroll
    for (int r = 0; r < NREP; r++) { g_cursor2[t * NREP + r] = a; a += c[r]; }
    g_counts[t] = total;
}

// ---------------- K3: scatter x into cluster-sorted order (4 pts/thread) ----------------
__global__ __launch_bounds__(256)
void k_scatter(const float* __restrict__ x) {
    int i0 = (blockIdx.x * 256 + threadIdx.x) * 4;
    if (i0 >= NPTS) return;
    unsigned pr = *(const unsigned*)(g_pred + i0);
    int rep = (((i0 >> 2) % NWARPS) >> 3) & (NREP - 1);
    int pos[4];
#pragma unroll
    for (int p = 0; p < 4; p++) {
        int k = (pr >> (8 * p)) & 255;
        pos[p] = atomicAdd(&g_cursor2[k * NREP + rep], 1);
    }
#pragma unroll
    for (int p = 0; p < 4; p++) {
        const float4* src = (const float4*)(x + (size_t)(i0 + p) * DD);
        float4* dst = (float4*)(g_xs + (size_t)pos[p] * DD);
#pragma unroll
        for (int q = 0; q < 8; q++) dst[q] = src[q];
    }
}

// ---------------- K4: uniform 64-row tiles over sorted array, segmented ----------------
// 2048 blocks x 128 threads; batch-4 load/compute phases force deep MLP;
// column sums spread over all threads (no warp-0 straggler).
__global__ __launch_bounds__(128)
void k_cov() {
    __shared__ float sx[TILE * DD];
    int t = threadIdx.x;
    int p0 = blockIdx.x * TILE;

    {   // coalesced tile load: 512 float4 / 128 threads = 4 each
        float4* sv = (float4*)sx;
        const float4* gv = (const float4*)g_xs + (size_t)p0 * (DD / 4);
#pragma unroll
        for (int v = 0; v < 4; v++) sv[v * 128 + t] = gv[v * 128 + t];
    }
    __syncthreads();

    // cluster containing row p0: largest c with offsets[c] <= p0
    int lo_c = 0, hi_c = KK;
    while (lo_c + 1 < hi_c) {
        int mid = (lo_c + hi_c) >> 1;
        if (g_offsets[mid] <= p0) lo_c = mid; else hi_c = mid;
    }
    int c = lo_c;

    int i = t >> 3;            // rows i, i+16
    int j0 = (t & 7) * 4;      // 4 cols
    int scol = t & 31;         // ssum: column
    int srg = t >> 5;          // ssum: row group [srg*16, srg*16+16)

    int segStart = p0;
    int tileEnd = p0 + TILE;
    while (segStart < tileEnd) {
        int segEnd = g_offsets[c + 1];
        if (segEnd > tileEnd) segEnd = tileEnd;
        int lo = segStart - p0, hi = segEnd - p0;
        if (hi > lo) {
            float a00 = 0.f, a01 = 0.f, a02 = 0.f, a03 = 0.f;
            float a10 = 0.f, a11 = 0.f, a12 = 0.f, a13 = 0.f;

            // spread column sums: each thread covers its 16-row slice
            {
                int slo = lo > srg * 16 ? lo : srg * 16;
                int shi = hi < srg * 16 + 16 ? hi : srg * 16 + 16;
                float ssum = 0.f;
                for (int p = slo; p < shi; p++) ssum += sx[p * DD + scol];
                if (shi > slo) atomicAdd(&g_sums[c * DD + scol], ssum);
            }

            if (lo == 0 && hi == TILE) {
#pragma unroll
                for (int pb = 0; pb < TILE; pb += 4) {
                    float R0[4], R1[4]; float4 BV[4];
#pragma unroll
                    for (int u = 0; u < 4; u++) {
                        R0[u] = sx[(pb + u) * DD + i];
                        R1[u] = sx[(pb + u) * DD + i + 16];
                        BV[u] = *(const float4*)(sx + (pb + u) * DD + j0);
                    }
#pragma unroll
                    for (int u = 0; u < 4; u++) {
                        a00 = fmaf(R0[u], BV[u].x, a00); a01 = fmaf(R0[u], BV[u].y, a01);
                        a02 = fmaf(R0[u], BV[u].z, a02); a03 = fmaf(R0[u], BV[u].w, a03);
                        a10 = fmaf(R1[u], BV[u].x, a10); a11 = fmaf(R1[u], BV[u].y, a11);
                        a12 = fmaf(R1[u], BV[u].z, a12); a13 = fmaf(R1[u], BV[u].w, a13);
                    }
                }
            } else {
                for (int p = lo; p < hi; p++) {
                    float r0 = sx[p * DD + i];
                    float r1 = sx[p * DD + i + 16];
                    float4 bv = *(const float4*)(sx + p * DD + j0);
                    a00 = fmaf(r0, bv.x, a00); a01 = fmaf(r0, bv.y, a01);
                    a02 = fmaf(r0, bv.z, a02); a03 = fmaf(r0, bv.w, a03);
                    a10 = fmaf(r1, bv.x, a10); a11 = fmaf(r1, bv.y, a11);
                    a12 = fmaf(r1, bv.z, a12); a13 = fmaf(r1, bv.w, a13);
                }
            }
            int base0 = c * DD * DD + i * DD + j0;
            int base1 = base0 + 16 * DD;
            atomicAdd(&g_m2[base0 + 0], a00); atomicAdd(&g_m2[base0 + 1], a01);
            atomicAdd(&g_m2[base0 + 2], a02); atomicAdd(&g_m2[base0 + 3], a03);
            atomicAdd(&g_m2[base1 + 0], a10); atomicAdd(&g_m2[base1 + 1], a11);
            atomicAdd(&g_m2[base1 + 2], a12); atomicAdd(&g_m2[base1 + 3], a13);
        }
        segStart = segEnd;
        c++;
    }
}

// ---------------- K5a: per-cluster stat loss partials (+re-zero m2/sums) ----------------
__global__ __launch_bounds__(256)
void k_stat(const float* __restrict__ means_t, const float* __restrict__ covs_t) {
    int k = blockIdx.x;
    int t = threadIdx.x;
    __shared__ float smean[DD];
    __shared__ float red[8];
    int cnt = g_counts[k];
    float inv = 1.0f / (float)(cnt > 0 ? cnt : 1);
    if (t < DD) smean[t] = g_sums[k * DD + t] * inv;
    __syncthreads();
    float lm = 0.f;
    if (t < DD) {
        float dm = smean[t] - means_t[k * DD + t];
        lm = dm * dm;
        g_sums[k * DD + t] = 0.f;
    }
    float lc = 0.f;
#pragma unroll
    for (int r = 0; r < 4; r++) {
        int idx = t + r * 256;
        int ii = idx >> 5, jj = idx & 31;
        float cov = g_m2[k * DD * DD + idx] * inv - smean[ii] * smean[jj];
        g_m2[k * DD * DD + idx] = 0.f;
        float dc = cov - covs_t[k * DD * DD + idx];
        lc = fmaf(dc, dc, lc);
    }
    float v = lm * (1.0f / (KK * DD)) + lc * (1.0f / (KK * DD * DD));
    v += __shfl_xor_sync(0xffffffffu, v, 16);
    v += __shfl_xor_sync(0xffffffffu, v, 8);
    v += __shfl_xor_sync(0xffffffffu, v, 4);
    v += __shfl_xor_sync(0xffffffffu, v, 2);
    v += __shfl_xor_sync(0xffffffffu, v, 1);
    if ((t & 31) == 0) red[t >> 5] = v;
    __syncthreads();
    if (t == 0) {
        float s = 0.f;
#pragma unroll
        for (int w = 0; w < 8; w++) s += red[w];
        atomicAdd(&g_acc[0], s);
    }
}

// ---------------- K5b: filling loss + final scalar (+re-zero fil/acc) ----------------
__global__ void k_final(const float* __restrict__ fil_t, float* __restrict__ out) {
    __shared__ float red[2];
    int t = threadIdx.x;  // 64 threads
    float f = g_fil[t] * (1.0f / NPTS) - fil_t[t];
    g_fil[t] = 0.f;
    float v = f * f;
    v += __shfl_xor_sync(0xffffffffu, v, 16);
    v += __shfl_xor_sync(0xffffffffu, v, 8);
    v += __shfl_xor_sync(0xffffffffu, v, 4);
    v += __shfl_xor_sync(0xffffffffu, v, 2);
    v += __shfl_xor_sync(0xffffffffu, v, 1);
    if ((t & 31) == 0) red[t >> 5] = v;
    __syncthreads();
    if (t == 0) {
        float a = g_acc[0];
        g_acc[0] = 0.f;
        out[0] = (red[0] + red[1]) * (1.0f / KK) + a;
    }
}

// ---------------- launcher (k_cov is profiled launch slot #4) ----------------
extern "C" void kernel_launch(void* const* d_in, const int* in_sizes, int n_in,
                              void* d_out, int out_size) {
    const float* x       = (const float*)d_in[0];
    const float* centers = (const float*)d_in[1];
    const float* fil_t   = (const float*)d_in[2];
    const float* means_t = (const float*)d_in[3];
    const float* covs_t  = (const float*)d_in[4];
    float* out = (float*)d_out;
    (void)in_sizes; (void)n_in; (void)out_size;

    k_assign<<<NBLK2, 256>>>(x, centers);
    k_prefix<<<1, 64>>>();
    k_scatter<<<NPTS / 1024, 256>>>(x);
    k_cov<<<NPTS / TILE, 128>>>();
    k_stat<<<KK, 256>>>(means_t, covs_t);
    k_final<<<1, 64>>>(fil_t, out);
}

// round 13
// speedup vs baseline: 7.6886x; 1.1686x over previous
#include <cuda_runtime.h>

#define NPTS 131072
#define DD 32
#define KK 64
#define B2E 14.426950408889634f  /* BETA * log2(e), BETA=10 */
#define NBLK2 740                /* k_assign grid: 5 blocks/SM */
#define NWARPS (NBLK2 * 8)       /* 5920 counting warps */
#define NREP 32                  /* scatter cursor replicas */
#define TILE 64                  /* k_cov tile rows */

// ---------------- device scratch (zero-initialized at load; every kernel
// leaves its accumulators re-zeroed => graph replays start clean) ----------
__device__ int   g_ord[NPTS];              // cluster-sorted permutation
__device__ unsigned char g_pred[NPTS];
__device__ int   g_counts[KK];
__device__ int   g_counts2[KK * NREP];
__device__ int   g_cursor2[KK * NREP];
__device__ int   g_offsets[KK + 1];
__device__ float g_fil[KK];
__device__ float g_sums[KK * DD];
__device__ float g_m2[KK * DD * DD];
__device__ float g_acc[2];

// order-preserving float<->u32 key (min of key == min of float, bijective)
__device__ __forceinline__ unsigned ordkey(float f) {
    unsigned u = __float_as_uint(f);
    return u ^ (unsigned)(((int)u >> 31) | 0x80000000);
}
__device__ __forceinline__ float unord(unsigned k) {
    unsigned u = (k & 0x80000000u) ? (k ^ 0x80000000u) : ~k;
    return __uint_as_float(u);
}

// ---------------- K1: logits, softmax-filling, argmin, histogram ----------------
__global__ __launch_bounds__(256, 5)
void k_assign(const float* __restrict__ x, const float* __restrict__ centers) {
    __shared__ float sc[KK * DD];     // swizzled centers
    __shared__ float scn[KK];
    __shared__ float sfil[KK];
    __shared__ int   shist[KK];
    __shared__ float sxw[8][4][DD];

    int t = threadIdx.x, w = t >> 5, l = t & 31;

#pragma unroll
    for (int v = 0; v < 2; v++) {
        int idx = v * 256 + t;
        int r = idx >> 3, q = idx & 7;
        float4 val = ((const float4*)centers)[idx];
        int qs = q ^ (r & 7);
        *(float4*)&sc[r * DD + qs * 4] = val;
    }
    __syncthreads();
    if (t < KK) {
        float a = 0.f;
#pragma unroll
        for (int q = 0; q < 8; q++) {
            int qs = q ^ (t & 7);
            float4 v = *(const float4*)&sc[t * DD + qs * 4];
            a = fmaf(v.x, v.x, fmaf(v.y, v.y, fmaf(v.z, v.z, fmaf(v.w, v.w, a))));
        }
        scn[t] = a;
        sfil[t] = 0.f; shist[t] = 0;
    }
    __syncthreads();

    float cn0 = scn[l], cn1 = scn[l + 32];
    const float* c0base = sc + l * DD;
    const float* c1base = sc + (l + 32) * DD;
    int sw = (l & 7);

    float fil0 = 0.f, fil1 = 0.f;
    int W = blockIdx.x * 8 + w;

    for (int n0 = W * 4; n0 < NPTS; n0 += NWARPS * 4) {
        float xp[4];
#pragma unroll
        for (int p = 0; p < 4; p++) xp[p] = x[(size_t)(n0 + p) * DD + l];
        __syncwarp();
#pragma unroll
        for (int p = 0; p < 4; p++) sxw[w][p][l] = xp[p];
        __syncwarp();

        float d0[4] = {0.f, 0.f, 0.f, 0.f};
        float d1[4] = {0.f, 0.f, 0.f, 0.f};
#pragma unroll
        for (int q = 0; q < 8; q++) {
            int qs = (q ^ sw) * 4;
            float4 cv0 = *(const float4*)&c0base[qs];
            float4 cv1 = *(const float4*)&c1base[qs];
#pragma unroll
            for (int p = 0; p < 4; p++) {
                float4 xv = *(const float4*)&sxw[w][p][q * 4];
                d0[p] = fmaf(cv0.x, xv.x, d0[p]);
                d0[p] = fmaf(cv0.y, xv.y, d0[p]);
                d0[p] = fmaf(cv0.z, xv.z, d0[p]);
                d0[p] = fmaf(cv0.w, xv.w, d0[p]);
                d1[p] = fmaf(cv1.x, xv.x, d1[p]);
                d1[p] = fmaf(cv1.y, xv.y, d1[p]);
                d1[p] = fmaf(cv1.z, xv.z, d1[p]);
                d1[p] = fmaf(cv1.w, xv.w, d1[p]);
            }
        }

        float s0a[4], s1a[4];
#pragma unroll
        for (int p = 0; p < 4; p++) {
            s0a[p] = fmaf(-2.f, d0[p], cn0);
            s1a[p] = fmaf(-2.f, d1[p], cn1);
        }

        unsigned k0v[4], k1v[4], mk[4];
#pragma unroll
        for (int p = 0; p < 4; p++) { k0v[p] = ordkey(s0a[p]); k1v[p] = ordkey(s1a[p]); }
#pragma unroll
        for (int p = 0; p < 4; p++)
            mk[p] = __reduce_min_sync(0xffffffffu, min(k0v[p], k1v[p]));
        int id[4];
#pragma unroll
        for (int p = 0; p < 4; p++) {
            unsigned cand = (k0v[p] == mk[p]) ? (unsigned)l
                          : ((k1v[p] == mk[p]) ? (unsigned)(l + 32) : 1024u);
            id[p] = (int)__reduce_min_sync(0xffffffffu, cand);
        }

        float e0[4], e1[4], es[4];
#pragma unroll
        for (int p = 0; p < 4; p++) {
            float mn = unord(mk[p]);
            asm("ex2.approx.f32 %0, %1;" : "=f"(e0[p]) : "f"((mn - s0a[p]) * B2E));
            asm("ex2.approx.f32 %0, %1;" : "=f"(e1[p]) : "f"((mn - s1a[p]) * B2E));
            es[p] = e0[p] + e1[p];
        }
#pragma unroll
        for (int off = 16; off; off >>= 1) {
#pragma unroll
            for (int p = 0; p < 4; p++)
                es[p] += __shfl_xor_sync(0xffffffffu, es[p], off);
        }

        unsigned pred4 = 0;
#pragma unroll
        for (int p = 0; p < 4; p++) {
            float inv;
            asm("rcp.approx.f32 %0, %1;" : "=f"(inv) : "f"(es[p]));
            fil0 = fmaf(e0[p], inv, fil0);
            fil1 = fmaf(e1[p], inv, fil1);
            pred4 |= (unsigned)id[p] << (8 * p);
            if (l == p) atomicAdd(&shist[id[p]], 1);
        }
        if (l == 0) *(unsigned*)(g_pred + n0) = pred4;
    }

    atomicAdd(&sfil[l], fil0);
    atomicAdd(&sfil[l + 32], fil1);
    __syncthreads();
    if (t < KK) {
        atomicAdd(&g_fil[t], sfil[t]);
        atomicAdd(&g_counts2[t * NREP + (blockIdx.x & (NREP - 1))], shist[t]);
    }
}

// ---------------- K2: prefix over 64 clusters x 32 replicas (+re-zero) ----------------
__global__ void k_prefix() {
    __shared__ int csum[KK];
    int t = threadIdx.x;   // 64 threads
    int c[NREP];
    int total = 0;
#pragma unroll
    for (int r = 0; r < NREP; r++) {
        c[r] = g_counts2[t * NREP + r];
        g_counts2[t * NREP + r] = 0;
        total += c[r];
    }
    csum[t] = total;
    __syncthreads();
    if (t == 0) {
        int a = 0;
        for (int k = 0; k < KK; k++) { g_offsets[k] = a; a += csum[k]; }
        g_offsets[KK] = a;
    }
    __syncthreads();
    int a = g_offsets[t];
#pragma unroll
    for (int r = 0; r < NREP; r++) { g_cursor2[t * NREP + r] = a; a += c[r]; }
    g_counts[t] = total;
}

// ---------------- K3: permutation only (no data movement) ----------------
__global__ __launch_bounds__(256)
void k_order() {
    int i0 = (blockIdx.x * 256 + threadIdx.x) * 4;
    if (i0 >= NPTS) return;
    unsigned pr = *(const unsigned*)(g_pred + i0);
    int rep = (((i0 >> 2) % NWARPS) >> 3) & (NREP - 1);
#pragma unroll
    for (int p = 0; p < 4; p++) {
        int k = (pr >> (8 * p)) & 255;
        int pos = atomicAdd(&g_cursor2[k * NREP + rep], 1);
        g_ord[pos] = i0 + p;
    }
}

// ---------------- K4: uniform 64-row tiles, gather via ord, double-buffered ----------------
__global__ __launch_bounds__(128, 8)
void k_cov(const float* __restrict__ x) {
    __shared__ float sx[TILE * DD];
    __shared__ int sord[TILE];
    int t = threadIdx.x;
    int p0 = blockIdx.x * TILE;

    if (t < TILE) sord[t] = g_ord[p0 + t];
    __syncthreads();

    {   // gather tile: 8 consecutive threads read same row, consecutive chunks
        float4* sv = (float4*)sx;
        const float4* xv = (const float4*)x;
#pragma unroll
        for (int v = 0; v < 4; v++) {
            int li = v * 128 + t;              // 0..511
            int row = li >> 3, chunk = li & 7;
            sv[li] = xv[(size_t)sord[row] * 8 + chunk];
        }
    }
    __syncthreads();

    // cluster containing row p0
    int lo_c = 0, hi_c = KK;
    while (lo_c + 1 < hi_c) {
        int mid = (lo_c + hi_c) >> 1;
        if (g_offsets[mid] <= p0) lo_c = mid; else hi_c = mid;
    }
    int c = lo_c;

    int i = t >> 3;            // rows i, i+16
    int j0 = (t & 7) * 4;      // 4 cols
    int scol = t & 31;         // ssum: column
    int srg = t >> 5;          // ssum: row group [srg*16, srg*16+16)

    int segStart = p0;
    int tileEnd = p0 + TILE;
    while (segStart < tileEnd) {
        int segEnd = g_offsets[c + 1];
        if (segEnd > tileEnd) segEnd = tileEnd;
        int lo = segStart - p0, hi = segEnd - p0;
        if (hi > lo) {
            float a00 = 0.f, a01 = 0.f, a02 = 0.f, a03 = 0.f;
            float a10 = 0.f, a11 = 0.f, a12 = 0.f, a13 = 0.f;

            {   // spread column sums
                int slo = lo > srg * 16 ? lo : srg * 16;
                int shi = hi < srg * 16 + 16 ? hi : srg * 16 + 16;
                float ssum = 0.f;
                for (int p = slo; p < shi; p++) ssum += sx[p * DD + scol];
                if (shi > slo) atomicAdd(&g_sums[c * DD + scol], ssum);
            }

            if (lo == 0 && hi == TILE) {
                // double-buffered 4-point batches: prefetch B while FMA-ing A
                float R0A[4], R1A[4]; float4 BVA[4];
#pragma unroll
                for (int u = 0; u < 4; u++) {
                    R0A[u] = sx[u * DD + i];
                    R1A[u] = sx[u * DD + i + 16];
                    BVA[u] = *(const float4*)(sx + u * DD + j0);
                }
#pragma unroll
                for (int pb = 0; pb < TILE; pb += 4) {
                    float R0B[4], R1B[4]; float4 BVB[4];
                    if (pb + 4 < TILE) {
#pragma unroll
                        for (int u = 0; u < 4; u++) {
                            R0B[u] = sx[(pb + 4 + u) * DD + i];
                            R1B[u] = sx[(pb + 4 + u) * DD + i + 16];
                            BVB[u] = *(const float4*)(sx + (pb + 4 + u) * DD + j0);
                        }
                    }
#pragma unroll
                    for (int u = 0; u < 4; u++) {
                        a00 = fmaf(R0A[u], BVA[u].x, a00); a01 = fmaf(R0A[u], BVA[u].y, a01);
                        a02 = fmaf(R0A[u], BVA[u].z, a02); a03 = fmaf(R0A[u], BVA[u].w, a03);
                        a10 = fmaf(R1A[u], BVA[u].x, a10); a11 = fmaf(R1A[u], BVA[u].y, a11);
                        a12 = fmaf(R1A[u], BVA[u].z, a12); a13 = fmaf(R1A[u], BVA[u].w, a13);
                    }
#pragma unroll
                    for (int u = 0; u < 4; u++) {
                        R0A[u] = R0B[u]; R1A[u] = R1B[u]; BVA[u] = BVB[u];
                    }
                }
            } else {
                for (int p = lo; p < hi; p++) {
                    float r0 = sx[p * DD + i];
                    float r1 = sx[p * DD + i + 16];
                    float4 bv = *(const float4*)(sx + p * DD + j0);
                    a00 = fmaf(r0, bv.x, a00); a01 = fmaf(r0, bv.y, a01);
                    a02 = fmaf(r0, bv.z, a02); a03 = fmaf(r0, bv.w, a03);
                    a10 = fmaf(r1, bv.x, a10); a11 = fmaf(r1, bv.y, a11);
                    a12 = fmaf(r1, bv.z, a12); a13 = fmaf(r1, bv.w, a13);
                }
            }
            int base0 = c * DD * DD + i * DD + j0;
            int base1 = base0 + 16 * DD;
            atomicAdd(&g_m2[base0 + 0], a00); atomicAdd(&g_m2[base0 + 1], a01);
            atomicAdd(&g_m2[base0 + 2], a02); atomicAdd(&g_m2[base0 + 3], a03);
            atomicAdd(&g_m2[base1 + 0], a10); atomicAdd(&g_m2[base1 + 1], a11);
            atomicAdd(&g_m2[base1 + 2], a12); atomicAdd(&g_m2[base1 + 3], a13);
        }
        segStart = segEnd;
        c++;
    }
}

// ---------------- K5a: per-cluster stat loss partials (+re-zero m2/sums) ----------------
__global__ __launch_bounds__(256)
void k_stat(const float* __restrict__ means_t, const float* __restrict__ covs_t) {
    int k = blockIdx.x;
    int t = threadIdx.x;
    __shared__ float smean[DD];
    __shared__ float red[8];
    int cnt = g_counts[k];
    float inv = 1.0f / (float)(cnt > 0 ? cnt : 1);
    if (t < DD) smean[t] = g_sums[k * DD + t] * inv;
    __syncthreads();
    float lm = 0.f;
    if (t < DD) {
        float dm = smean[t] - means_t[k * DD + t];
        lm = dm * dm;
        g_sums[k * DD + t] = 0.f;
    }
    float lc = 0.f;
#pragma unroll
    for (int r = 0; r < 4; r++) {
        int idx = t + r * 256;
        int ii = idx >> 5, jj = idx & 31;
        float cov = g_m2[k * DD * DD + idx] * inv - smean[ii] * smean[jj];
        g_m2[k * DD * DD + idx] = 0.f;
        float dc = cov - covs_t[k * DD * DD + idx];
        lc = fmaf(dc, dc, lc);
    }
    float v = lm * (1.0f / (KK * DD)) + lc * (1.0f / (KK * DD * DD));
    v += __shfl_xor_sync(0xffffffffu, v, 16);
    v += __shfl_xor_sync(0xffffffffu, v, 8);
    v += __shfl_xor_sync(0xffffffffu, v, 4);
    v += __shfl_xor_sync(0xffffffffu, v, 2);
    v += __shfl_xor_sync(0xffffffffu, v, 1);
    if ((t & 31) == 0) red[t >> 5] = v;
    __syncthreads();
    if (t == 0) {
        float s = 0.f;
#pragma unroll
        for (int w = 0; w < 8; w++) s += red[w];
        atomicAdd(&g_acc[0], s);
    }
}

// ---------------- K5b: filling loss + final scalar (+re-zero fil/acc) ----------------
__global__ void k_final(const float* __restrict__ fil_t, float* __restrict__ out) {
    __shared__ float red[2];
    int t = threadIdx.x;  // 64 threads
    float f = g_fil[t] * (1.0f / NPTS) - fil_t[t];
    g_fil[t] = 0.f;
    float v = f * f;
    v += __shfl_xor_sync(0xffffffffu, v, 16);
    v += __shfl_xor_sync(0xffffffffu, v, 8);
    v += __shfl_xor_sync(0xffffffffu, v, 4);
    v += __shfl_xor_sync(0xffffffffu, v, 2);
    v += __shfl_xor_sync(0xffffffffu, v, 1);
    if ((t & 31) == 0) red[t >> 5] = v;
    __syncthreads();
    if (t == 0) {
        float a = g_acc[0];
        g_acc[0] = 0.f;
        out[0] = (red[0] + red[1]) * (1.0f / KK) + a;
    }
}

// ---------------- launcher (k_cov is profiled launch slot #4) ----------------
extern "C" void kernel_launch(void* const* d_in, const int* in_sizes, int n_in,
                              void* d_out, int out_size) {
    const float* x       = (const float*)d_in[0];
    const float* centers = (const float*)d_in[1];
    const float* fil_t   = (const float*)d_in[2];
    const float* means_t = (const float*)d_in[3];
    const float* covs_t  = (const float*)d_in[4];
    float* out = (float*)d_out;
    (void)in_sizes; (void)n_in; (void)out_size;

    k_assign<<<NBLK2, 256>>>(x, centers);
    k_prefix<<<1, 64>>>();
    k_order<<<NPTS / 1024, 256>>>();
    k_cov<<<NPTS / TILE, 128>>>(x);
    k_stat<<<KK, 256>>>(means_t, covs_t);
    k_final<<<1, 64>>>(fil_t, out);
}